// round 9
// baseline (speedup 1.0000x reference)
#include <cuda_runtime.h>
#include <cuda_bf16.h>
#include <math.h>
#include <stdint.h>

// ---------------- problem constants ----------------
#define D_MODEL   2048
#define NUM_HEADS 16
#define HEAD_DIM  128
#define BATCH     2
#define SEQ       2048
#define MROWS     (BATCH * SEQ)        // 4096

#define NELEM_X   (MROWS * D_MODEL)          // 8388608
#define NELEM_W   (D_MODEL * D_MODEL)        // 4194304
#define NELEM_WKV (D_MODEL * HEAD_DIM)       // 262144
#define NELEM_KV  (MROWS * HEAD_DIM)         // 524288

// ---------------- scratch (__device__ statics; no cudaMalloc) ----------
__device__ __align__(16) __nv_bfloat16 g_xq_h[NELEM_X], g_xq_l[NELEM_X];
__device__ __align__(16) __nv_bfloat16 g_xk_h[NELEM_X], g_xk_l[NELEM_X];
__device__ __align__(16) __nv_bfloat16 g_xv_h[NELEM_X], g_xv_l[NELEM_X];
__device__ __align__(16) __nv_bfloat16 g_wq_h[NELEM_W], g_wq_l[NELEM_W];   // [N,K]
__device__ __align__(16) __nv_bfloat16 g_wk_h[NELEM_WKV], g_wk_l[NELEM_WKV];
__device__ __align__(16) __nv_bfloat16 g_wv_h[NELEM_WKV], g_wv_l[NELEM_WKV];
__device__ __align__(16) __nv_bfloat16 g_wo_h[NELEM_W], g_wo_l[NELEM_W];
__device__ __align__(16) __nv_bfloat16 g_q_h[NELEM_X],  g_q_l[NELEM_X];    // pre-scaled Q
__device__ __align__(16) __nv_bfloat16 g_k_h[NELEM_KV], g_k_l[NELEM_KV];   // [b*s, d]
__device__ __align__(16) __nv_bfloat16 g_vt_h[NELEM_KV], g_vt_l[NELEM_KV]; // [b][d, s]
__device__ __align__(16) __nv_bfloat16 g_a_h[NELEM_X], g_a_l[NELEM_X];     // attn out

// ---------------- low-level helpers (baseline sm_80+ ISA only) ----------
__device__ __forceinline__ uint32_t smem_to_u32(const void* p) {
    uint32_t a;
    asm("{ .reg .u64 t; cvta.to.shared.u64 t, %1; cvt.u32.u64 %0, t; }" : "=r"(a) : "l"(p));
    return a;
}
#define CP16(dst, src) \
    asm volatile("cp.async.cg.shared.global [%0], [%1], 16;" :: "r"(dst), "l"(src))
#define CP_COMMIT() asm volatile("cp.async.commit_group;" ::: "memory")
#define CP_WAIT(n)  asm volatile("cp.async.wait_group %0;" :: "n"(n) : "memory")

__device__ __forceinline__ void ldsm4(uint32_t* r, uint32_t addr) {
    asm volatile("ldmatrix.sync.aligned.m8n8.x4.shared.b16 {%0,%1,%2,%3}, [%4];"
        : "=r"(r[0]), "=r"(r[1]), "=r"(r[2]), "=r"(r[3]) : "r"(addr));
}
__device__ __forceinline__ void mma16816(float* c, const uint32_t* a, const uint32_t* b) {
    asm volatile("mma.sync.aligned.m16n8k16.row.col.f32.bf16.bf16.f32 "
        "{%0,%1,%2,%3}, {%4,%5,%6,%7}, {%8,%9}, {%0,%1,%2,%3};"
        : "+f"(c[0]), "+f"(c[1]), "+f"(c[2]), "+f"(c[3])
        : "r"(a[0]), "r"(a[1]), "r"(a[2]), "r"(a[3]), "r"(b[0]), "r"(b[1]));
}

__device__ __forceinline__ void split2(float t0, float t1,
                                       __nv_bfloat162& hi, __nv_bfloat162& lo) {
    __nv_bfloat16 h0 = __float2bfloat16(t0);
    __nv_bfloat16 h1 = __float2bfloat16(t1);
    hi.x = h0; hi.y = h1;
    lo.x = __float2bfloat16(t0 - __bfloat162float(h0));
    lo.y = __float2bfloat16(t1 - __bfloat162float(h1));
}

// swizzled smem offset for (row r, 16B-chunk c) within a 64B-wide tile block
__device__ __forceinline__ uint32_t sw_off(int r, int c) {
    return (uint32_t)(r * 64 + ((c ^ ((r >> 1) & 3)) << 4));
}

// =====================================================================
// Conversion kernels
// =====================================================================
__global__ void __launch_bounds__(256)
conv_all(const float* __restrict__ q, const float* __restrict__ k,
         const float* __restrict__ v,
         __nv_bfloat16* __restrict__ qh, __nv_bfloat16* __restrict__ ql,
         __nv_bfloat16* __restrict__ kh, __nv_bfloat16* __restrict__ kl,
         __nv_bfloat16* __restrict__ vh, __nv_bfloat16* __restrict__ vl)
{
    const int z = blockIdx.y;
    const float* x = (z == 0) ? q : (z == 1) ? k : v;
    __nv_bfloat16* h = (z == 0) ? qh : (z == 1) ? kh : vh;
    __nv_bfloat16* l = (z == 0) ? ql : (z == 1) ? kl : vl;
    const int i = blockIdx.x * 256 + threadIdx.x;
    float4 val = ((const float4*)x)[i];
    __nv_bfloat162 h0, h1, l0, l1;
    split2(val.x, val.y, h0, l0);
    split2(val.z, val.w, h1, l1);
    ((__nv_bfloat162*)h)[i * 2]     = h0;
    ((__nv_bfloat162*)h)[i * 2 + 1] = h1;
    ((__nv_bfloat162*)l)[i * 2]     = l0;
    ((__nv_bfloat162*)l)[i * 2 + 1] = l1;
}

// W [K,N] row-major -> T [N,K] hi/lo
__device__ __forceinline__ void convT_body(
    const float* __restrict__ W, __nv_bfloat16* __restrict__ Th,
    __nv_bfloat16* __restrict__ Tl, int Kd, int Nd)
{
    __shared__ float t[32][33];
    const int n0 = blockIdx.x * 32, k0 = blockIdx.y * 32;
    const int tx = threadIdx.x & 31, ty = threadIdx.x >> 5;
#pragma unroll
    for (int i = 0; i < 4; i++)
        t[ty + i * 8][tx] = W[(size_t)(k0 + ty + i * 8) * Nd + n0 + tx];
    __syncthreads();
#pragma unroll
    for (int i = 0; i < 4; i++) {
        float v = t[tx][ty + i * 8];
        __nv_bfloat16 h = __float2bfloat16(v);
        size_t o = (size_t)(n0 + ty + i * 8) * Kd + k0 + tx;
        Th[o] = h;
        Tl[o] = __float2bfloat16(v - __bfloat162float(h));
    }
}

__global__ void __launch_bounds__(256)
convT_big(const float* __restrict__ Wq, const float* __restrict__ Wo,
          __nv_bfloat16* __restrict__ qh, __nv_bfloat16* __restrict__ ql,
          __nv_bfloat16* __restrict__ oh, __nv_bfloat16* __restrict__ ol)
{
    if (blockIdx.z == 0) convT_body(Wq, qh, ql, D_MODEL, D_MODEL);
    else                 convT_body(Wo, oh, ol, D_MODEL, D_MODEL);
}

__global__ void __launch_bounds__(256)
convT_small(const float* __restrict__ Wk, const float* __restrict__ Wv,
            __nv_bfloat16* __restrict__ kh, __nv_bfloat16* __restrict__ kl,
            __nv_bfloat16* __restrict__ vh, __nv_bfloat16* __restrict__ vl)
{
    if (blockIdx.z == 0) convT_body(Wk, kh, kl, D_MODEL, HEAD_DIM);
    else                 convT_body(Wv, vh, vl, D_MODEL, HEAD_DIM);
}

// =====================================================================
// WIDE split-bf16 GEMM: CTA 128x256, warp tile 64x64, BK=32, 4 stages.
// 85 B smem traffic per MMA (vs 128 at 64x32) -> higher tensor util.
// EPI: 0 = fp32+bias, 1 = split-bf16(+bias,*scale).
// =====================================================================
#define WST_AH  0
#define WST_AL  8192
#define WST_BH  16384
#define WST_BL  32768
#define WSTAGE  49152
#define WSM_BYTES (4 * WSTAGE)        // 196608

template<int EPI>
__global__ void __launch_bounds__(256, 1)
gemm_wide(const __nv_bfloat16* __restrict__ Ah, const __nv_bfloat16* __restrict__ Al,
          const __nv_bfloat16* __restrict__ Bh, const __nv_bfloat16* __restrict__ Bl,
          const float* __restrict__ bias,
          float* __restrict__ Cf, __nv_bfloat16* __restrict__ Ch, __nv_bfloat16* __restrict__ Cl,
          int K, int lda, int ldb, int ldc, float scale)
{
    extern __shared__ char smem[];
    const uint32_t sb = smem_to_u32(smem);
    const int tid = threadIdx.x, lane = tid & 31, wid = tid >> 5;
    const int wm = wid & 1, wn = wid >> 1;           // 2 x 4 warps, tile 64x64
    const int row0 = blockIdx.y * 128, col0 = blockIdx.x * 256;

    const char* pAh = (const char*)(Ah + (size_t)row0 * lda);
    const char* pAl = (const char*)(Al + (size_t)row0 * lda);
    const char* pBh = (const char*)(Bh + (size_t)col0 * ldb);
    const char* pBl = (const char*)(Bl + (size_t)col0 * ldb);
    const size_t lda2 = (size_t)lda * 2, ldb2 = (size_t)ldb * 2;

    float acc[4][8][4];
#pragma unroll
    for (int a = 0; a < 4; a++)
#pragma unroll
        for (int b = 0; b < 8; b++)
#pragma unroll
            for (int c = 0; c < 4; c++) acc[a][b][c] = 0.0f;

    const int niter = K >> 5;

#define LOAD_W(s, kof) do {                                                  \
        const uint32_t bA = sb + (uint32_t)(s) * WSTAGE;                     \
        const size_t kb = (size_t)(kof) * 2;                                 \
        _Pragma("unroll")                                                    \
        for (int ii = 0; ii < 2; ii++) {                                     \
            const int idx = tid + ii * 256;                                  \
            const int r = idx >> 2, c = idx & 3;                             \
            const uint32_t o = sw_off(r, c);                                 \
            CP16(bA + WST_AH + o, pAh + r * lda2 + kb + c * 16);             \
            CP16(bA + WST_AL + o, pAl + r * lda2 + kb + c * 16);             \
        }                                                                    \
        _Pragma("unroll")                                                    \
        for (int ii = 0; ii < 4; ii++) {                                     \
            const int idx = tid + ii * 256;                                  \
            const int r = idx >> 2, c = idx & 3;                             \
            const uint32_t o = sw_off(r, c);                                 \
            CP16(bA + WST_BH + o, pBh + r * ldb2 + kb + c * 16);             \
            CP16(bA + WST_BL + o, pBl + r * ldb2 + kb + c * 16);             \
        }                                                                    \
    } while (0)

    LOAD_W(0, 0);  CP_COMMIT();
    LOAD_W(1, 32); CP_COMMIT();
    LOAD_W(2, 64); CP_COMMIT();

    for (int i = 0; i < niter; i++) {
        if (i < niter - 2)       { CP_WAIT(2); }
        else if (i == niter - 2) { CP_WAIT(1); }
        else                     { CP_WAIT(0); }
        __syncthreads();
        if (i + 3 < niter) { LOAD_W((i + 3) & 3, (i + 3) * 32); CP_COMMIT(); }

        const uint32_t sA = sb + (uint32_t)(i & 3) * WSTAGE;
#pragma unroll
        for (int h = 0; h < 2; h++) {
            const int chk = 2 * h + (lane >> 4);
            uint32_t ah[4][4], al[4][4];
#pragma unroll
            for (int mt = 0; mt < 4; mt++) {
                const int r = wm * 64 + mt * 16 + (lane & 15);
                const uint32_t off = sw_off(r, chk);
                ldsm4(ah[mt], sA + WST_AH + off);
                ldsm4(al[mt], sA + WST_AL + off);
            }
#pragma unroll
            for (int np = 0; np < 4; np++) {
                uint32_t bh4[4], bl4[4];
                const int r = wn * 64 + np * 16 + (lane & 15);
                const uint32_t off = sw_off(r, chk);
                ldsm4(bh4, sA + WST_BH + off);
                ldsm4(bl4, sA + WST_BL + off);
#pragma unroll
                for (int mt = 0; mt < 4; mt++)
#pragma unroll
                    for (int sel = 0; sel < 2; sel++) {
                        const int nt = np * 2 + sel;
                        uint32_t bfh[2] = { bh4[sel], bh4[sel + 2] };
                        uint32_t bfl[2] = { bl4[sel], bl4[sel + 2] };
                        mma16816(acc[mt][nt], ah[mt], bfh);
                        mma16816(acc[mt][nt], ah[mt], bfl);
                        mma16816(acc[mt][nt], al[mt], bfh);
                    }
            }
        }
    }
#undef LOAD_W

    // ---------------- epilogue ----------------
#pragma unroll
    for (int mt = 0; mt < 4; mt++) {
#pragma unroll
        for (int nt = 0; nt < 8; nt++) {
            const float* a = acc[mt][nt];
            const int gr = row0 + wm * 64 + mt * 16 + (lane >> 2);
            const int gc = col0 + wn * 64 + nt * 8 + (lane & 3) * 2;
            if (EPI == 0) {
                float b0 = bias[gc], b1 = bias[gc + 1];
                float2 v0 = { a[0] + b0, a[1] + b1 };
                float2 v1 = { a[2] + b0, a[3] + b1 };
                *(float2*)&Cf[(size_t)gr * ldc + gc]       = v0;
                *(float2*)&Cf[(size_t)(gr + 8) * ldc + gc] = v1;
            } else {
                const float b0 = bias[gc], b1 = bias[gc + 1];
                __nv_bfloat162 hh, ll;
                split2((a[0] + b0) * scale, (a[1] + b1) * scale, hh, ll);
                size_t o = (size_t)gr * ldc + gc;
                *(__nv_bfloat162*)&Ch[o] = hh;
                *(__nv_bfloat162*)&Cl[o] = ll;
                split2((a[2] + b0) * scale, (a[3] + b1) * scale, hh, ll);
                o = (size_t)(gr + 8) * ldc + gc;
                *(__nv_bfloat162*)&Ch[o] = hh;
                *(__nv_bfloat162*)&Cl[o] = ll;
            }
        }
    }
}

// =====================================================================
// Narrow split-bf16 GEMM body (128x128, BK=32, 3 stages) for K/V proj.
// EPI: 1 = split-bf16(+bias), 3 = split-bf16 transposed V^T store.
// =====================================================================
#define STAGES     3
#define STAGE_B    32768
#define GSM_BYTES  (STAGES * STAGE_B)

template<int EPI>
__device__ __forceinline__ void gemm_body(
         const __nv_bfloat16* __restrict__ Ah, const __nv_bfloat16* __restrict__ Al,
         const __nv_bfloat16* __restrict__ Bh, const __nv_bfloat16* __restrict__ Bl,
         const float* __restrict__ bias,
         __nv_bfloat16* __restrict__ Ch, __nv_bfloat16* __restrict__ Cl,
         int K, int lda, int ldb, int ldc)
{
    extern __shared__ char smem[];
    const uint32_t sb = smem_to_u32(smem);
    const int tid = threadIdx.x, lane = tid & 31, wid = tid >> 5;
    const int wm = wid & 1, wn = wid >> 1;
    const int row0 = blockIdx.y * 128, col0 = blockIdx.x * 128;

    const char* pAh = (const char*)(Ah + (size_t)row0 * lda);
    const char* pAl = (const char*)(Al + (size_t)row0 * lda);
    const char* pBh = (const char*)(Bh + (size_t)col0 * ldb);
    const char* pBl = (const char*)(Bl + (size_t)col0 * ldb);
    const size_t lda2 = (size_t)lda * 2, ldb2 = (size_t)ldb * 2;

    const int r0c = tid >> 2,            c0c = tid & 3;
    const int r1c = (tid + 256) >> 2,    c1c = (tid + 256) & 3;
    const uint32_t so0 = sw_off(r0c, c0c), so1 = sw_off(r1c, c1c);

    float acc[4][4][4];
#pragma unroll
    for (int a = 0; a < 4; a++)
#pragma unroll
        for (int b = 0; b < 4; b++)
#pragma unroll
            for (int c = 0; c < 4; c++) acc[a][b][c] = 0.0f;

    const int niter = K >> 5;

#define LOAD_STAGE(s, kof) do {                                              \
        const uint32_t bA = sb + (s) * STAGE_B;                              \
        const size_t kb = (size_t)(kof) * 2;                                 \
        CP16(bA + so0,         pAh + r0c * lda2 + kb + c0c * 16);            \
        CP16(bA + so1,         pAh + r1c * lda2 + kb + c1c * 16);            \
        CP16(bA + 8192 + so0,  pAl + r0c * lda2 + kb + c0c * 16);            \
        CP16(bA + 8192 + so1,  pAl + r1c * lda2 + kb + c1c * 16);            \
        CP16(bA + 16384 + so0, pBh + r0c * ldb2 + kb + c0c * 16);            \
        CP16(bA + 16384 + so1, pBh + r1c * ldb2 + kb + c1c * 16);            \
        CP16(bA + 24576 + so0, pBl + r0c * ldb2 + kb + c0c * 16);            \
        CP16(bA + 24576 + so1, pBl + r1c * ldb2 + kb + c1c * 16);            \
    } while (0)

    LOAD_STAGE(0, 0);  CP_COMMIT();
    LOAD_STAGE(1, 32); CP_COMMIT();

    for (int i = 0; i < niter; i++) {
        if (i < niter - 1) { CP_WAIT(1); } else { CP_WAIT(0); }
        __syncthreads();
        if (i + 2 < niter) { LOAD_STAGE((i + 2) % STAGES, (i + 2) * 32); CP_COMMIT(); }

        const uint32_t sA = sb + (i % STAGES) * STAGE_B;
        const uint32_t sB = sA + 16384;
#pragma unroll
        for (int h = 0; h < 2; h++) {
            uint32_t ah[4][4], al[4][4], bh[2][4], bl[2][4];
            const int chk = 2 * h + (lane >> 4);
#pragma unroll
            for (int mt = 0; mt < 4; mt++) {
                const int r = wm * 64 + mt * 16 + (lane & 15);
                const uint32_t off = sw_off(r, chk);
                ldsm4(ah[mt], sA + off);
                ldsm4(al[mt], sA + 8192 + off);
            }
#pragma unroll
            for (int np = 0; np < 2; np++) {
                const int r = wn * 32 + np * 16 + (lane & 15);
                const uint32_t off = sw_off(r, chk);
                ldsm4(bh[np], sB + off);
                ldsm4(bl[np], sB + 8192 + off);
            }
#pragma unroll
            for (int mt = 0; mt < 4; mt++)
#pragma unroll
                for (int nt = 0; nt < 4; nt++) {
                    const int np = nt >> 1, sel = nt & 1;
                    uint32_t bfh[2] = { bh[np][sel], bh[np][sel + 2] };
                    uint32_t bfl[2] = { bl[np][sel], bl[np][sel + 2] };
                    mma16816(acc[mt][nt], ah[mt], bfh);
                    mma16816(acc[mt][nt], ah[mt], bfl);
                    mma16816(acc[mt][nt], al[mt], bfh);
                }
        }
    }
#undef LOAD_STAGE

#pragma unroll
    for (int mt = 0; mt < 4; mt++) {
#pragma unroll
        for (int nt = 0; nt < 4; nt++) {
            const float* a = acc[mt][nt];
            const int gr = row0 + wm * 64 + mt * 16 + (lane >> 2);
            const int gc = col0 + wn * 32 + nt * 8 + (lane & 3) * 2;
            if (EPI == 1) {
                const float b0 = bias[gc], b1 = bias[gc + 1];
                __nv_bfloat162 hh, ll;
                split2(a[0] + b0, a[1] + b1, hh, ll);
                size_t o = (size_t)gr * ldc + gc;
                *(__nv_bfloat162*)&Ch[o] = hh;
                *(__nv_bfloat162*)&Cl[o] = ll;
                split2(a[2] + b0, a[3] + b1, hh, ll);
                o = (size_t)(gr + 8) * ldc + gc;
                *(__nv_bfloat162*)&Ch[o] = hh;
                *(__nv_bfloat162*)&Cl[o] = ll;
            } else {  // EPI == 3: V^T store: out[b][dim][token]
#pragma unroll
                for (int q = 0; q < 4; q++) {
                    const int rr = gr + (q >> 1) * 8;
                    const int cc = gc + (q & 1);
                    const float t = a[q] + bias[cc];
                    const __nv_bfloat16 h = __float2bfloat16(t);
                    const size_t o = (size_t)(rr >> 11) * ((size_t)HEAD_DIM * SEQ)
                                   + (size_t)cc * SEQ + (rr & (SEQ - 1));
                    Ch[o] = h;
                    Cl[o] = __float2bfloat16(t - __bfloat162float(h));
                }
            }
        }
    }
}

// K and V projections z-fused (z=0: K normal store, z=1: V transposed store)
__global__ void __launch_bounds__(256, 2)
kv_proj(const __nv_bfloat16* __restrict__ xkh, const __nv_bfloat16* __restrict__ xkl,
        const __nv_bfloat16* __restrict__ xvh, const __nv_bfloat16* __restrict__ xvl,
        const __nv_bfloat16* __restrict__ wkh, const __nv_bfloat16* __restrict__ wkl,
        const __nv_bfloat16* __restrict__ wvh, const __nv_bfloat16* __restrict__ wvl,
        const float* __restrict__ bk, const float* __restrict__ bv,
        __nv_bfloat16* __restrict__ kh, __nv_bfloat16* __restrict__ kl,
        __nv_bfloat16* __restrict__ vth, __nv_bfloat16* __restrict__ vtl)
{
    if (blockIdx.z == 0)
        gemm_body<1>(xkh, xkl, wkh, wkl, bk, kh, kl,
                     D_MODEL, D_MODEL, D_MODEL, HEAD_DIM);
    else
        gemm_body<3>(xvh, xvl, wvh, wvl, bv, vth, vtl,
                     D_MODEL, D_MODEL, D_MODEL, 0);
}

// =====================================================================
// Fused flash attention (split-bf16 mma.sync, online softmax).
// CTA: 128 q rows x full KV sweep. 8 warps x 16 rows. KT=64 per iter.
// =====================================================================
#define FL_STAGE  65536
#define FL_SMEM   (2 * FL_STAGE)     // 131072

__global__ void __launch_bounds__(256)
flash_mma(const __nv_bfloat16* __restrict__ Qh, const __nv_bfloat16* __restrict__ Ql,
          const __nv_bfloat16* __restrict__ Kh, const __nv_bfloat16* __restrict__ Kl,
          const __nv_bfloat16* __restrict__ Vth, const __nv_bfloat16* __restrict__ Vtl,
          __nv_bfloat16* __restrict__ Oh, __nv_bfloat16* __restrict__ Ol)
{
    extern __shared__ char smem[];
    const uint32_t sb = smem_to_u32(smem);
    const int tid = threadIdx.x, lane = tid & 31, w = tid >> 5;
    const int q0 = blockIdx.x * 128;
    const int hh = blockIdx.y;
    const int b  = blockIdx.z;

    const char* pQh = (const char*)(Qh + ((size_t)(b * SEQ) + q0) * D_MODEL + hh * HEAD_DIM);
    const char* pQl = (const char*)(Ql + ((size_t)(b * SEQ) + q0) * D_MODEL + hh * HEAD_DIM);
    const char* pKh = (const char*)(Kh + (size_t)b * SEQ * HEAD_DIM);
    const char* pKl = (const char*)(Kl + (size_t)b * SEQ * HEAD_DIM);
    const char* pVh = (const char*)(Vth + (size_t)b * HEAD_DIM * SEQ);
    const char* pVl = (const char*)(Vtl + (size_t)b * HEAD_DIM * SEQ);

#define LOAD_KV(stg, kv0) do {                                               \
        const uint32_t bb = sb + (uint32_t)(stg) * FL_STAGE;                 \
        _Pragma("unroll")                                                    \
        for (int i2 = 0; i2 < 4; i2++) {                                     \
            const int idx = tid + i2 * 256;                                  \
            const int r = idx >> 4, c = idx & 15;                            \
            const uint32_t d = bb + ((c >> 2) << 12) + sw_off(r, c & 3);     \
            const size_t so = (size_t)((kv0) + r) * 256 + (c & 3) * 16 + (c >> 2) * 64; \
            CP16(d,         pKh + so);                                       \
            CP16(d + 16384, pKl + so);                                       \
        }                                                                    \
        _Pragma("unroll")                                                    \
        for (int i2 = 0; i2 < 4; i2++) {                                     \
            const int idx = tid + i2 * 256;                                  \
            const int r = idx >> 3, c = idx & 7;                             \
            const uint32_t d = bb + 32768 + ((c >> 2) << 13) + sw_off(r, c & 3); \
            const size_t so = (size_t)r * (SEQ * 2) + (size_t)(kv0) * 2 + (c & 3) * 16 + (c >> 2) * 64; \
            CP16(d,         pVh + so);                                       \
            CP16(d + 16384, pVl + so);                                       \
        }                                                                    \
    } while (0)

    // stage Q into stage-1 region
#pragma unroll
    for (int i2 = 0; i2 < 8; i2++) {
        const int idx = tid + i2 * 256;
        const int r = idx >> 4, c = idx & 15;
        const uint32_t d = sb + FL_STAGE + ((c >> 2) << 13) + sw_off(r, c & 3);
        const size_t so = (size_t)r * (D_MODEL * 2) + (c & 3) * 16 + (c >> 2) * 64;
        CP16(d,         pQh + so);
        CP16(d + 32768, pQl + so);
    }
    CP_COMMIT();
    LOAD_KV(0, 0);
    CP_COMMIT();

    CP_WAIT(1);
    __syncthreads();

    // Q fragments (A operand, m16 x k128): 8 k-steps, hi + lo
    uint32_t qfh[8][4], qfl[8][4];
#pragma unroll
    for (int ks = 0; ks < 8; ks++) {
        const int blk = ks >> 1;
        const int c   = (ks & 1) * 2 + (lane >> 4);
        const int r   = w * 16 + (lane & 15);
        const uint32_t a = sb + FL_STAGE + (blk << 13) + sw_off(r, c);
        ldsm4(qfh[ks], a);
        ldsm4(qfl[ks], a + 32768);
    }

    float oacc[16][4];
#pragma unroll
    for (int nt = 0; nt < 16; nt++)
#pragma unroll
        for (int q = 0; q < 4; q++) oacc[nt][q] = 0.0f;
    float m0 = -1e30f, m1 = -1e30f, l0 = 0.0f, l1 = 0.0f;

    for (int it = 0; it < SEQ / 64; it++) {
        CP_WAIT(0);
        __syncthreads();
        if (it + 1 < SEQ / 64) { LOAD_KV((it + 1) & 1, (it + 1) * 64); CP_COMMIT(); }

        const uint32_t kb = sb + (uint32_t)(it & 1) * FL_STAGE;
        const uint32_t vb = kb + 32768;

        // -------- scores: S[16q x 64kv] --------
        float sacc[8][4];
#pragma unroll
        for (int nt = 0; nt < 8; nt++)
#pragma unroll
            for (int q = 0; q < 4; q++) sacc[nt][q] = 0.0f;

#pragma unroll
        for (int ks = 0; ks < 8; ks++) {
            const int blk = ks >> 1;
            const int cc  = (ks & 1) * 2 + (lane >> 4);
#pragma unroll
            for (int g = 0; g < 4; g++) {
                uint32_t bh4[4], bl4[4];
                const int r = g * 16 + (lane & 15);
                const uint32_t a = kb + (blk << 12) + sw_off(r, cc);
                ldsm4(bh4, a);
                ldsm4(bl4, a + 16384);
#pragma unroll
                for (int sel = 0; sel < 2; sel++) {
                    const int nt = g * 2 + sel;
                    uint32_t fh[2] = { bh4[sel], bh4[sel + 2] };
                    uint32_t fl[2] = { bl4[sel], bl4[sel + 2] };
                    mma16816(sacc[nt], qfh[ks], fh);
                    mma16816(sacc[nt], qfh[ks], fl);
                    mma16816(sacc[nt], qfl[ks], fh);
                }
            }
        }

        // -------- online softmax --------
        float mx0 = sacc[0][0], mx1 = sacc[0][2];
#pragma unroll
        for (int nt = 0; nt < 8; nt++) {
            mx0 = fmaxf(mx0, fmaxf(sacc[nt][0], sacc[nt][1]));
            mx1 = fmaxf(mx1, fmaxf(sacc[nt][2], sacc[nt][3]));
        }
        mx0 = fmaxf(mx0, __shfl_xor_sync(0xffffffffu, mx0, 1));
        mx0 = fmaxf(mx0, __shfl_xor_sync(0xffffffffu, mx0, 2));
        mx1 = fmaxf(mx1, __shfl_xor_sync(0xffffffffu, mx1, 1));
        mx1 = fmaxf(mx1, __shfl_xor_sync(0xffffffffu, mx1, 2));
        const float mn0 = fmaxf(m0, mx0), mn1 = fmaxf(m1, mx1);
        const float cr0 = __expf(m0 - mn0), cr1 = __expf(m1 - mn1);
        m0 = mn0; m1 = mn1;

        float s0 = 0.0f, s1 = 0.0f;
        uint32_t php[8][2], plp[8][2];
#pragma unroll
        for (int nt = 0; nt < 8; nt++) {
            const float p0 = __expf(sacc[nt][0] - mn0);
            const float p1 = __expf(sacc[nt][1] - mn0);
            const float p2 = __expf(sacc[nt][2] - mn1);
            const float p3 = __expf(sacc[nt][3] - mn1);
            s0 += p0 + p1;
            s1 += p2 + p3;
            __nv_bfloat162 hx, lx;
            split2(p0, p1, hx, lx);
            php[nt][0] = *(uint32_t*)&hx;  plp[nt][0] = *(uint32_t*)&lx;
            split2(p2, p3, hx, lx);
            php[nt][1] = *(uint32_t*)&hx;  plp[nt][1] = *(uint32_t*)&lx;
        }
        s0 += __shfl_xor_sync(0xffffffffu, s0, 1);
        s0 += __shfl_xor_sync(0xffffffffu, s0, 2);
        s1 += __shfl_xor_sync(0xffffffffu, s1, 1);
        s1 += __shfl_xor_sync(0xffffffffu, s1, 2);
        l0 = l0 * cr0 + s0;
        l1 = l1 * cr1 + s1;

#pragma unroll
        for (int nt = 0; nt < 16; nt++) {
            oacc[nt][0] *= cr0; oacc[nt][1] *= cr0;
            oacc[nt][2] *= cr1; oacc[nt][3] *= cr1;
        }

        // -------- PV: out[16q x 128d] += P[16 x 64] * V[64 x 128] --------
#pragma unroll
        for (int kk = 0; kk < 4; kk++) {
            uint32_t aph[4] = { php[2 * kk][0], php[2 * kk][1],
                                php[2 * kk + 1][0], php[2 * kk + 1][1] };
            uint32_t apl[4] = { plp[2 * kk][0], plp[2 * kk][1],
                                plp[2 * kk + 1][0], plp[2 * kk + 1][1] };
            const int blk = kk >> 1;
            const int cc  = (kk & 1) * 2 + (lane >> 4);
#pragma unroll
            for (int g = 0; g < 8; g++) {
                uint32_t vh4[4], vl4[4];
                const int r = g * 16 + (lane & 15);
                const uint32_t a = vb + (blk << 13) + sw_off(r, cc);
                ldsm4(vh4, a);
                ldsm4(vl4, a + 16384);
#pragma unroll
                for (int sel = 0; sel < 2; sel++) {
                    const int nt = g * 2 + sel;
                    uint32_t fh[2] = { vh4[sel], vh4[sel + 2] };
                    uint32_t fl[2] = { vl4[sel], vl4[sel + 2] };
                    mma16816(oacc[nt], aph, fh);
                    mma16816(oacc[nt], aph, fl);
                    mma16816(oacc[nt], apl, fh);
                }
            }
        }
    }
#undef LOAD_KV

    // -------- epilogue: normalize + split-bf16 store --------
    const float i0 = 1.0f / l0, i1 = 1.0f / l1;
    const size_t ro0 = ((size_t)(b * SEQ) + q0 + w * 16 + (lane >> 2)) * D_MODEL
                     + (size_t)hh * HEAD_DIM;
    const size_t ro1 = ro0 + (size_t)8 * D_MODEL;
#pragma unroll
    for (int nt = 0; nt < 16; nt++) {
        const int col = nt * 8 + (lane & 3) * 2;
        __nv_bfloat162 hx, lx;
        split2(oacc[nt][0] * i0, oacc[nt][1] * i0, hx, lx);
        *(__nv_bfloat162*)&Oh[ro0 + col] = hx;
        *(__nv_bfloat162*)&Ol[ro0 + col] = lx;
        split2(oacc[nt][2] * i1, oacc[nt][3] * i1, hx, lx);
        *(__nv_bfloat162*)&Oh[ro1 + col] = hx;
        *(__nv_bfloat162*)&Ol[ro1 + col] = lx;
    }
}

// =====================================================================
// launch
// =====================================================================
extern "C" void kernel_launch(void* const* d_in, const int* in_sizes, int n_in,
                              void* d_out, int out_size)
{
    const float* query = (const float*)d_in[0];
    const float* key   = (const float*)d_in[1];
    const float* value = (const float*)d_in[2];
    const float* Wq    = (const float*)d_in[3];
    const float* bq    = (const float*)d_in[4];
    const float* Wk    = (const float*)d_in[5];
    const float* bk    = (const float*)d_in[6];
    const float* Wv    = (const float*)d_in[7];
    const float* bv    = (const float*)d_in[8];
    const float* Wo    = (const float*)d_in[9];
    const float* bo    = (const float*)d_in[10];
    float* out = (float*)d_out;

    __nv_bfloat16 *xqh, *xql, *xkh, *xkl, *xvh, *xvl;
    __nv_bfloat16 *wqh, *wql, *wkh, *wkl, *wvh, *wvl, *woh, *wol;
    __nv_bfloat16 *qh, *ql, *kh, *kl, *vth, *vtl, *ah, *al;
    cudaGetSymbolAddress((void**)&xqh, g_xq_h);  cudaGetSymbolAddress((void**)&xql, g_xq_l);
    cudaGetSymbolAddress((void**)&xkh, g_xk_h);  cudaGetSymbolAddress((void**)&xkl, g_xk_l);
    cudaGetSymbolAddress((void**)&xvh, g_xv_h);  cudaGetSymbolAddress((void**)&xvl, g_xv_l);
    cudaGetSymbolAddress((void**)&wqh, g_wq_h);  cudaGetSymbolAddress((void**)&wql, g_wq_l);
    cudaGetSymbolAddress((void**)&wkh, g_wk_h);  cudaGetSymbolAddress((void**)&wkl, g_wk_l);
    cudaGetSymbolAddress((void**)&wvh, g_wv_h);  cudaGetSymbolAddress((void**)&wvl, g_wv_l);
    cudaGetSymbolAddress((void**)&woh, g_wo_h);  cudaGetSymbolAddress((void**)&wol, g_wo_l);
    cudaGetSymbolAddress((void**)&qh,  g_q_h);   cudaGetSymbolAddress((void**)&ql,  g_q_l);
    cudaGetSymbolAddress((void**)&kh,  g_k_h);   cudaGetSymbolAddress((void**)&kl,  g_k_l);
    cudaGetSymbolAddress((void**)&vth, g_vt_h);  cudaGetSymbolAddress((void**)&vtl, g_vt_l);
    cudaGetSymbolAddress((void**)&ah,  g_a_h);   cudaGetSymbolAddress((void**)&al,  g_a_l);

    cudaFuncSetAttribute(gemm_wide<0>, cudaFuncAttributeMaxDynamicSharedMemorySize, WSM_BYTES);
    cudaFuncSetAttribute(gemm_wide<1>, cudaFuncAttributeMaxDynamicSharedMemorySize, WSM_BYTES);
    cudaFuncSetAttribute(kv_proj,      cudaFuncAttributeMaxDynamicSharedMemorySize, GSM_BYTES);
    cudaFuncSetAttribute(flash_mma,    cudaFuncAttributeMaxDynamicSharedMemorySize, FL_SMEM);

    const float attn_scale = 0.08838834764831845f;  // 1/sqrt(128)

    // 1) input conversions (one launch, z = q/k/v)
    conv_all<<<dim3(NELEM_X / 1024, 3), 256>>>(query, key, value,
                                               xqh, xql, xkh, xkl, xvh, xvl);

    // 2) weight transpose+split conversions
    convT_big<<<dim3(D_MODEL / 32, D_MODEL / 32, 2), 256>>>(Wq, Wo, wqh, wql, woh, wol);
    convT_small<<<dim3(HEAD_DIM / 32, D_MODEL / 32, 2), 256>>>(Wk, Wv, wkh, wkl, wvh, wvl);

    // 3) Q projection (scaled by 1/sqrt(d), split output) - wide tile
    gemm_wide<1><<<dim3(D_MODEL / 256, MROWS / 128), 256, WSM_BYTES>>>(
        xqh, xql, wqh, wql, bq, nullptr, qh, ql,
        D_MODEL, D_MODEL, D_MODEL, D_MODEL, attn_scale);

    // 4) K + V projections (z-fused; V stored transposed) - narrow tile
    kv_proj<<<dim3(1, MROWS / 128, 2), 256, GSM_BYTES>>>(
        xkh, xkl, xvh, xvl, wkh, wkl, wvh, wvl, bk, bv, kh, kl, vth, vtl);

    // 5) fused flash attention -> split-bf16 attn output
    flash_mma<<<dim3(SEQ / 128, NUM_HEADS, BATCH), 256, FL_SMEM>>>(
        qh, ql, kh, kl, vth, vtl, ah, al);

    // 6) output projection -> d_out (fp32 + bias) - wide tile
    gemm_wide<0><<<dim3(D_MODEL / 256, MROWS / 128), 256, WSM_BYTES>>>(
        ah, al, woh, wol, bo, out, nullptr, nullptr,
        D_MODEL, D_MODEL, D_MODEL, D_MODEL, 1.0f);
}

// round 10
// speedup vs baseline: 1.4303x; 1.4303x over previous
#include <cuda_runtime.h>
#include <cuda_fp16.h>
#include <math.h>
#include <stdint.h>

// ---------------- problem constants ----------------
#define D_MODEL   2048
#define NUM_HEADS 16
#define HEAD_DIM  128
#define BATCH     2
#define SEQ       2048
#define MROWS     (BATCH * SEQ)        // 4096

#define NELEM_X   (MROWS * D_MODEL)          // 8388608
#define NELEM_W   (D_MODEL * D_MODEL)        // 4194304
#define NELEM_WKV (D_MODEL * HEAD_DIM)       // 262144
#define NELEM_KV  (MROWS * HEAD_DIM)         // 524288

// ---------------- scratch (__device__ statics; no cudaMalloc) ----------
__device__ __align__(16) __half g_xq_h[NELEM_X], g_xq_l[NELEM_X];
__device__ __align__(16) __half g_xk_h[NELEM_X], g_xk_l[NELEM_X];
__device__ __align__(16) __half g_xv_h[NELEM_X], g_xv_l[NELEM_X];
__device__ __align__(16) __half g_wq[NELEM_W];        // [N,K] single fp16
__device__ __align__(16) __half g_wk[NELEM_WKV];
__device__ __align__(16) __half g_wv[NELEM_WKV];
__device__ __align__(16) __half g_wo[NELEM_W];
__device__ __align__(16) __half g_q_h[NELEM_X],  g_q_l[NELEM_X];   // pre-scaled Q hi/lo
__device__ __align__(16) __half g_k[NELEM_KV];                      // K single [b*s, d]
__device__ __align__(16) __half g_vt[NELEM_KV];                     // V^T single [b][d, s]
__device__ __align__(16) __half g_a_h[NELEM_X], g_a_l[NELEM_X];     // attn out hi/lo

// ---------------- low-level helpers ----------
__device__ __forceinline__ uint32_t smem_to_u32(const void* p) {
    uint32_t a;
    asm("{ .reg .u64 t; cvta.to.shared.u64 t, %1; cvt.u32.u64 %0, t; }" : "=r"(a) : "l"(p));
    return a;
}
#define CP16(dst, src) \
    asm volatile("cp.async.cg.shared.global [%0], [%1], 16;" :: "r"(dst), "l"(src))
#define CP_COMMIT() asm volatile("cp.async.commit_group;" ::: "memory")
#define CP_WAIT(n)  asm volatile("cp.async.wait_group %0;" :: "n"(n) : "memory")

__device__ __forceinline__ void ldsm4(uint32_t* r, uint32_t addr) {
    asm volatile("ldmatrix.sync.aligned.m8n8.x4.shared.b16 {%0,%1,%2,%3}, [%4];"
        : "=r"(r[0]), "=r"(r[1]), "=r"(r[2]), "=r"(r[3]) : "r"(addr));
}
// fp16 inputs, fp32 accumulate
__device__ __forceinline__ void mma16816h(float* c, const uint32_t* a, const uint32_t* b) {
    asm volatile("mma.sync.aligned.m16n8k16.row.col.f32.f16.f16.f32 "
        "{%0,%1,%2,%3}, {%4,%5,%6,%7}, {%8,%9}, {%0,%1,%2,%3};"
        : "+f"(c[0]), "+f"(c[1]), "+f"(c[2]), "+f"(c[3])
        : "r"(a[0]), "r"(a[1]), "r"(a[2]), "r"(a[3]), "r"(b[0]), "r"(b[1]));
}

__device__ __forceinline__ void split2h(float t0, float t1, __half2& hi, __half2& lo) {
    __half h0 = __float2half(t0);
    __half h1 = __float2half(t1);
    hi = __halves2half2(h0, h1);
    lo = __halves2half2(__float2half(t0 - __half2float(h0)),
                        __float2half(t1 - __half2float(h1)));
}

// swizzled smem offset for (row r, 16B-chunk c) within a 64B-wide tile block
__device__ __forceinline__ uint32_t sw_off(int r, int c) {
    return (uint32_t)(r * 64 + ((c ^ ((r >> 1) & 3)) << 4));
}

// =====================================================================
// Conversion kernels
// =====================================================================
__global__ void __launch_bounds__(256)
conv_all(const float* __restrict__ q, const float* __restrict__ k,
         const float* __restrict__ v,
         __half* __restrict__ qh, __half* __restrict__ ql,
         __half* __restrict__ kh, __half* __restrict__ kl,
         __half* __restrict__ vh, __half* __restrict__ vl)
{
    const int z = blockIdx.y;
    const float* x = (z == 0) ? q : (z == 1) ? k : v;
    __half* h = (z == 0) ? qh : (z == 1) ? kh : vh;
    __half* l = (z == 0) ? ql : (z == 1) ? kl : vl;
    const int i = blockIdx.x * 256 + threadIdx.x;
    float4 val = ((const float4*)x)[i];
    __half2 h0, h1, l0, l1;
    split2h(val.x, val.y, h0, l0);
    split2h(val.z, val.w, h1, l1);
    ((__half2*)h)[i * 2]     = h0;
    ((__half2*)h)[i * 2 + 1] = h1;
    ((__half2*)l)[i * 2]     = l0;
    ((__half2*)l)[i * 2 + 1] = l1;
}

// W [K,N] row-major -> T [N,K] single fp16
__device__ __forceinline__ void convT_body(
    const float* __restrict__ W, __half* __restrict__ Th, int Kd, int Nd)
{
    __shared__ float t[32][33];
    const int n0 = blockIdx.x * 32, k0 = blockIdx.y * 32;
    const int tx = threadIdx.x & 31, ty = threadIdx.x >> 5;
#pragma unroll
    for (int i = 0; i < 4; i++)
        t[ty + i * 8][tx] = W[(size_t)(k0 + ty + i * 8) * Nd + n0 + tx];
    __syncthreads();
#pragma unroll
    for (int i = 0; i < 4; i++) {
        float v = t[tx][ty + i * 8];
        Th[(size_t)(n0 + ty + i * 8) * Kd + k0 + tx] = __float2half(v);
    }
}

__global__ void __launch_bounds__(256)
convT_big(const float* __restrict__ Wq, const float* __restrict__ Wo,
          __half* __restrict__ wq, __half* __restrict__ wo)
{
    if (blockIdx.z == 0) convT_body(Wq, wq, D_MODEL, D_MODEL);
    else                 convT_body(Wo, wo, D_MODEL, D_MODEL);
}

__global__ void __launch_bounds__(256)
convT_small(const float* __restrict__ Wk, const float* __restrict__ Wv,
            __half* __restrict__ wk, __half* __restrict__ wv)
{
    if (blockIdx.z == 0) convT_body(Wk, wk, D_MODEL, HEAD_DIM);
    else                 convT_body(Wv, wv, D_MODEL, HEAD_DIM);
}

// =====================================================================
// 2-term split-fp16 GEMM: C[M,N] = (Ah+Al)[M,K] @ B[N,K]^T (+bias)(*scale)
// CTA 128x128, BK=32, 3-stage cp.async, 8 warps (64x32 warp tile).
// 2 MMAs per (mt,nt) per k16 (vs 3 in split-bf16): AhB + AlB.
// EPI: 0 = fp32+bias, 1 = fp16 hi/lo (+bias,*scale),
//      2 = fp16 single (+bias), 3 = fp16 single transposed V^T (+bias).
// =====================================================================
#define STAGES     3
#define STAGE_B    24576                      // Ah 8K | Al 8K | Bh 8K
#define GSM_BYTES  (STAGES * STAGE_B)         // 73728 -> 2 CTAs/SM

template<int EPI>
__device__ __forceinline__ void gemm_body(
         const __half* __restrict__ Ah, const __half* __restrict__ Al,
         const __half* __restrict__ Bh,
         const float* __restrict__ bias,
         float* __restrict__ Cf, __half* __restrict__ Ch, __half* __restrict__ Cl,
         int K, int lda, int ldb, int ldc, float scale)
{
    extern __shared__ char smem[];
    const uint32_t sb = smem_to_u32(smem);
    const int tid = threadIdx.x, lane = tid & 31, wid = tid >> 5;
    const int wm = wid & 1, wn = wid >> 1;
    const int row0 = blockIdx.y * 128, col0 = blockIdx.x * 128;

    const char* pAh = (const char*)(Ah + (size_t)row0 * lda);
    const char* pAl = (const char*)(Al + (size_t)row0 * lda);
    const char* pBh = (const char*)(Bh + (size_t)col0 * ldb);
    const size_t lda2 = (size_t)lda * 2, ldb2 = (size_t)ldb * 2;

    const int r0c = tid >> 2,            c0c = tid & 3;
    const int r1c = (tid + 256) >> 2,    c1c = (tid + 256) & 3;
    const uint32_t so0 = sw_off(r0c, c0c), so1 = sw_off(r1c, c1c);

    float acc[4][4][4];
#pragma unroll
    for (int a = 0; a < 4; a++)
#pragma unroll
        for (int b = 0; b < 4; b++)
#pragma unroll
            for (int c = 0; c < 4; c++) acc[a][b][c] = 0.0f;

    const int niter = K >> 5;

#define LOAD_STAGE(s, kof) do {                                              \
        const uint32_t bA = sb + (s) * STAGE_B;                              \
        const size_t kb = (size_t)(kof) * 2;                                 \
        CP16(bA + so0,         pAh + r0c * lda2 + kb + c0c * 16);            \
        CP16(bA + so1,         pAh + r1c * lda2 + kb + c1c * 16);            \
        CP16(bA + 8192 + so0,  pAl + r0c * lda2 + kb + c0c * 16);            \
        CP16(bA + 8192 + so1,  pAl + r1c * lda2 + kb + c1c * 16);            \
        CP16(bA + 16384 + so0, pBh + r0c * ldb2 + kb + c0c * 16);            \
        CP16(bA + 16384 + so1, pBh + r1c * ldb2 + kb + c1c * 16);            \
    } while (0)

    LOAD_STAGE(0, 0);  CP_COMMIT();
    LOAD_STAGE(1, 32); CP_COMMIT();

    for (int i = 0; i < niter; i++) {
        if (i < niter - 1) { CP_WAIT(1); } else { CP_WAIT(0); }
        __syncthreads();
        if (i + 2 < niter) { LOAD_STAGE((i + 2) % STAGES, (i + 2) * 32); CP_COMMIT(); }

        const uint32_t sA = sb + (i % STAGES) * STAGE_B;
        const uint32_t sB = sA + 16384;
#pragma unroll
        for (int h = 0; h < 2; h++) {
            uint32_t ah[4][4], al[4][4], bh[2][4];
            const int chk = 2 * h + (lane >> 4);
#pragma unroll
            for (int mt = 0; mt < 4; mt++) {
                const int r = wm * 64 + mt * 16 + (lane & 15);
                const uint32_t off = sw_off(r, chk);
                ldsm4(ah[mt], sA + off);
                ldsm4(al[mt], sA + 8192 + off);
            }
#pragma unroll
            for (int np = 0; np < 2; np++) {
                const int r = wn * 32 + np * 16 + (lane & 15);
                ldsm4(bh[np], sB + sw_off(r, chk));
            }
#pragma unroll
            for (int mt = 0; mt < 4; mt++)
#pragma unroll
                for (int nt = 0; nt < 4; nt++) {
                    const int np = nt >> 1, sel = nt & 1;
                    uint32_t bf[2] = { bh[np][sel], bh[np][sel + 2] };
                    mma16816h(acc[mt][nt], ah[mt], bf);
                    mma16816h(acc[mt][nt], al[mt], bf);
                }
        }
    }
#undef LOAD_STAGE

    // ---------------- epilogue ----------------
#pragma unroll
    for (int mt = 0; mt < 4; mt++) {
#pragma unroll
        for (int nt = 0; nt < 4; nt++) {
            const float* a = acc[mt][nt];
            const int gr = row0 + wm * 64 + mt * 16 + (lane >> 2);
            const int gc = col0 + wn * 32 + nt * 8 + (lane & 3) * 2;
            if (EPI == 0) {
                float b0 = bias[gc], b1 = bias[gc + 1];
                float2 v0 = { a[0] + b0, a[1] + b1 };
                float2 v1 = { a[2] + b0, a[3] + b1 };
                *(float2*)&Cf[(size_t)gr * ldc + gc]       = v0;
                *(float2*)&Cf[(size_t)(gr + 8) * ldc + gc] = v1;
            } else if (EPI == 1) {
                const float b0 = bias[gc], b1 = bias[gc + 1];
                __half2 hh, ll;
                split2h((a[0] + b0) * scale, (a[1] + b1) * scale, hh, ll);
                size_t o = (size_t)gr * ldc + gc;
                *(__half2*)&Ch[o] = hh;
                *(__half2*)&Cl[o] = ll;
                split2h((a[2] + b0) * scale, (a[3] + b1) * scale, hh, ll);
                o = (size_t)(gr + 8) * ldc + gc;
                *(__half2*)&Ch[o] = hh;
                *(__half2*)&Cl[o] = ll;
            } else if (EPI == 2) {
                const float b0 = bias[gc], b1 = bias[gc + 1];
                size_t o = (size_t)gr * ldc + gc;
                *(__half2*)&Ch[o] = __halves2half2(__float2half(a[0] + b0),
                                                   __float2half(a[1] + b1));
                o = (size_t)(gr + 8) * ldc + gc;
                *(__half2*)&Ch[o] = __halves2half2(__float2half(a[2] + b0),
                                                   __float2half(a[3] + b1));
            } else {  // EPI == 3: V^T single store: out[b][dim][token]
#pragma unroll
                for (int q = 0; q < 4; q++) {
                    const int rr = gr + (q >> 1) * 8;
                    const int cc = gc + (q & 1);
                    const float t = a[q] + bias[cc];
                    const size_t o = (size_t)(rr >> 11) * ((size_t)HEAD_DIM * SEQ)
                                   + (size_t)cc * SEQ + (rr & (SEQ - 1));
                    Ch[o] = __float2half(t);
                }
            }
        }
    }
}

template<int EPI>
__global__ void __launch_bounds__(256, 2)
gemm_mma(const __half* __restrict__ Ah, const __half* __restrict__ Al,
         const __half* __restrict__ Bh, const float* __restrict__ bias,
         float* __restrict__ Cf, __half* __restrict__ Ch, __half* __restrict__ Cl,
         int K, int lda, int ldb, int ldc, float scale)
{
    gemm_body<EPI>(Ah, Al, Bh, bias, Cf, Ch, Cl, K, lda, ldb, ldc, scale);
}

// K and V projections z-fused (z=0: K single store, z=1: V^T single store)
__global__ void __launch_bounds__(256, 2)
kv_proj(const __half* __restrict__ xkh, const __half* __restrict__ xkl,
        const __half* __restrict__ xvh, const __half* __restrict__ xvl,
        const __half* __restrict__ wk, const __half* __restrict__ wv,
        const float* __restrict__ bk, const float* __restrict__ bv,
        __half* __restrict__ k, __half* __restrict__ vt)
{
    if (blockIdx.z == 0)
        gemm_body<2>(xkh, xkl, wk, bk, nullptr, k, nullptr,
                     D_MODEL, D_MODEL, D_MODEL, HEAD_DIM, 1.0f);
    else
        gemm_body<3>(xvh, xvl, wv, bv, nullptr, vt, nullptr,
                     D_MODEL, D_MODEL, D_MODEL, 0, 1.0f);
}

// =====================================================================
// Fused flash attention (2-term split-fp16, online softmax).
// CTA: 128 q rows x full KV sweep. 8 warps x 16 rows. KT=64 per iter.
// K, V single fp16; Q and P split hi/lo.
// smem: 2 stages x 32KB (K 16K | Vt 16K), Q hi 32K @65536, Q lo 32K @98304.
// =====================================================================
#define FL_STAGE  32768
#define FL_Q      65536
#define FL_SMEM   131072

__global__ void __launch_bounds__(256)
flash_mma(const __half* __restrict__ Qh, const __half* __restrict__ Ql,
          const __half* __restrict__ Kg, const __half* __restrict__ Vtg,
          __half* __restrict__ Oh, __half* __restrict__ Ol)
{
    extern __shared__ char smem[];
    const uint32_t sb = smem_to_u32(smem);
    const int tid = threadIdx.x, lane = tid & 31, w = tid >> 5;
    const int q0 = blockIdx.x * 128;
    const int hh = blockIdx.y;
    const int b  = blockIdx.z;

    const char* pQh = (const char*)(Qh + ((size_t)(b * SEQ) + q0) * D_MODEL + hh * HEAD_DIM);
    const char* pQl = (const char*)(Ql + ((size_t)(b * SEQ) + q0) * D_MODEL + hh * HEAD_DIM);
    const char* pK  = (const char*)(Kg + (size_t)b * SEQ * HEAD_DIM);
    const char* pV  = (const char*)(Vtg + (size_t)b * HEAD_DIM * SEQ);

#define LOAD_KV(stg, kv0) do {                                               \
        const uint32_t bb = sb + (uint32_t)(stg) * FL_STAGE;                 \
        _Pragma("unroll")                                                    \
        for (int i2 = 0; i2 < 4; i2++) {                                     \
            const int idx = tid + i2 * 256;                                  \
            const int r = idx >> 4, c = idx & 15;                            \
            const uint32_t d = bb + ((c >> 2) << 12) + sw_off(r, c & 3);     \
            const size_t so = (size_t)((kv0) + r) * 256 + (c & 3) * 16 + (c >> 2) * 64; \
            CP16(d, pK + so);                                                \
        }                                                                    \
        _Pragma("unroll")                                                    \
        for (int i2 = 0; i2 < 4; i2++) {                                     \
            const int idx = tid + i2 * 256;                                  \
            const int r = idx >> 3, c = idx & 7;                             \
            const uint32_t d = bb + 16384 + ((c >> 2) << 13) + sw_off(r, c & 3); \
            const size_t so = (size_t)r * (SEQ * 2) + (size_t)(kv0) * 2 + (c & 3) * 16 + (c >> 2) * 64; \
            CP16(d, pV + so);                                                \
        }                                                                    \
    } while (0)

    // stage Q (hi and lo) once
#pragma unroll
    for (int i2 = 0; i2 < 8; i2++) {
        const int idx = tid + i2 * 256;
        const int r = idx >> 4, c = idx & 15;
        const uint32_t d = sb + FL_Q + ((c >> 2) << 13) + sw_off(r, c & 3);
        const size_t so = (size_t)r * (D_MODEL * 2) + (c & 3) * 16 + (c >> 2) * 64;
        CP16(d,         pQh + so);
        CP16(d + 32768, pQl + so);
    }
    CP_COMMIT();
    LOAD_KV(0, 0);
    CP_COMMIT();

    CP_WAIT(1);
    __syncthreads();

    // Q fragments: 8 k-steps, hi + lo
    uint32_t qfh[8][4], qfl[8][4];
#pragma unroll
    for (int ks = 0; ks < 8; ks++) {
        const int blk = ks >> 1;
        const int c   = (ks & 1) * 2 + (lane >> 4);
        const int r   = w * 16 + (lane & 15);
        const uint32_t a = sb + FL_Q + (blk << 13) + sw_off(r, c);
        ldsm4(qfh[ks], a);
        ldsm4(qfl[ks], a + 32768);
    }

    float oacc[16][4];
#pragma unroll
    for (int nt = 0; nt < 16; nt++)
#pragma unroll
        for (int q = 0; q < 4; q++) oacc[nt][q] = 0.0f;
    float m0 = -1e30f, m1 = -1e30f, l0 = 0.0f, l1 = 0.0f;

    for (int it = 0; it < SEQ / 64; it++) {
        CP_WAIT(0);
        __syncthreads();
        if (it + 1 < SEQ / 64) { LOAD_KV((it + 1) & 1, (it + 1) * 64); CP_COMMIT(); }

        const uint32_t kb = sb + (uint32_t)(it & 1) * FL_STAGE;
        const uint32_t vb = kb + 16384;

        // -------- scores: S[16q x 64kv] = (Qh+Ql) K^T --------
        float sacc[8][4];
#pragma unroll
        for (int nt = 0; nt < 8; nt++)
#pragma unroll
            for (int q = 0; q < 4; q++) sacc[nt][q] = 0.0f;

#pragma unroll
        for (int ks = 0; ks < 8; ks++) {
            const int blk = ks >> 1;
            const int cc  = (ks & 1) * 2 + (lane >> 4);
#pragma unroll
            for (int g = 0; g < 4; g++) {
                uint32_t kh4[4];
                const int r = g * 16 + (lane & 15);
                ldsm4(kh4, kb + (blk << 12) + sw_off(r, cc));
#pragma unroll
                for (int sel = 0; sel < 2; sel++) {
                    const int nt = g * 2 + sel;
                    uint32_t f[2] = { kh4[sel], kh4[sel + 2] };
                    mma16816h(sacc[nt], qfh[ks], f);
                    mma16816h(sacc[nt], qfl[ks], f);
                }
            }
        }

        // -------- online softmax --------
        float mx0 = sacc[0][0], mx1 = sacc[0][2];
#pragma unroll
        for (int nt = 0; nt < 8; nt++) {
            mx0 = fmaxf(mx0, fmaxf(sacc[nt][0], sacc[nt][1]));
            mx1 = fmaxf(mx1, fmaxf(sacc[nt][2], sacc[nt][3]));
        }
        mx0 = fmaxf(mx0, __shfl_xor_sync(0xffffffffu, mx0, 1));
        mx0 = fmaxf(mx0, __shfl_xor_sync(0xffffffffu, mx0, 2));
        mx1 = fmaxf(mx1, __shfl_xor_sync(0xffffffffu, mx1, 1));
        mx1 = fmaxf(mx1, __shfl_xor_sync(0xffffffffu, mx1, 2));
        const float mn0 = fmaxf(m0, mx0), mn1 = fmaxf(m1, mx1);
        const float cr0 = __expf(m0 - mn0), cr1 = __expf(m1 - mn1);
        m0 = mn0; m1 = mn1;

        float s0 = 0.0f, s1 = 0.0f;
        uint32_t php[8][2], plp[8][2];
#pragma unroll
        for (int nt = 0; nt < 8; nt++) {
            const float p0 = __expf(sacc[nt][0] - mn0);
            const float p1 = __expf(sacc[nt][1] - mn0);
            const float p2 = __expf(sacc[nt][2] - mn1);
            const float p3 = __expf(sacc[nt][3] - mn1);
            s0 += p0 + p1;
            s1 += p2 + p3;
            __half2 hx, lx;
            split2h(p0, p1, hx, lx);
            php[nt][0] = *(uint32_t*)&hx;  plp[nt][0] = *(uint32_t*)&lx;
            split2h(p2, p3, hx, lx);
            php[nt][1] = *(uint32_t*)&hx;  plp[nt][1] = *(uint32_t*)&lx;
        }
        s0 += __shfl_xor_sync(0xffffffffu, s0, 1);
        s0 += __shfl_xor_sync(0xffffffffu, s0, 2);
        s1 += __shfl_xor_sync(0xffffffffu, s1, 1);
        s1 += __shfl_xor_sync(0xffffffffu, s1, 2);
        l0 = l0 * cr0 + s0;
        l1 = l1 * cr1 + s1;

#pragma unroll
        for (int nt = 0; nt < 16; nt++) {
            oacc[nt][0] *= cr0; oacc[nt][1] *= cr0;
            oacc[nt][2] *= cr1; oacc[nt][3] *= cr1;
        }

        // -------- PV: out += (Ph+Pl)[16x64] V[64x128] --------
#pragma unroll
        for (int kk = 0; kk < 4; kk++) {
            uint32_t aph[4] = { php[2 * kk][0], php[2 * kk][1],
                                php[2 * kk + 1][0], php[2 * kk + 1][1] };
            uint32_t apl[4] = { plp[2 * kk][0], plp[2 * kk][1],
                                plp[2 * kk + 1][0], plp[2 * kk + 1][1] };
            const int blk = kk >> 1;
            const int cc  = (kk & 1) * 2 + (lane >> 4);
#pragma unroll
            for (int g = 0; g < 8; g++) {
                uint32_t vh4[4];
                const int r = g * 16 + (lane & 15);
                ldsm4(vh4, vb + (blk << 13) + sw_off(r, cc));
#pragma unroll
                for (int sel = 0; sel < 2; sel++) {
                    const int nt = g * 2 + sel;
                    uint32_t f[2] = { vh4[sel], vh4[sel + 2] };
                    mma16816h(oacc[nt], aph, f);
                    mma16816h(oacc[nt], apl, f);
                }
            }
        }
    }
#undef LOAD_KV

    // -------- epilogue: normalize + split-fp16 store --------
    const float i0 = 1.0f / l0, i1 = 1.0f / l1;
    const size_t ro0 = ((size_t)(b * SEQ) + q0 + w * 16 + (lane >> 2)) * D_MODEL
                     + (size_t)hh * HEAD_DIM;
    const size_t ro1 = ro0 + (size_t)8 * D_MODEL;
#pragma unroll
    for (int nt = 0; nt < 16; nt++) {
        const int col = nt * 8 + (lane & 3) * 2;
        __half2 hx, lx;
        split2h(oacc[nt][0] * i0, oacc[nt][1] * i0, hx, lx);
        *(__half2*)&Oh[ro0 + col] = hx;
        *(__half2*)&Ol[ro0 + col] = lx;
        split2h(oacc[nt][2] * i1, oacc[nt][3] * i1, hx, lx);
        *(__half2*)&Oh[ro1 + col] = hx;
        *(__half2*)&Ol[ro1 + col] = lx;
    }
}

// =====================================================================
// launch
// =====================================================================
extern "C" void kernel_launch(void* const* d_in, const int* in_sizes, int n_in,
                              void* d_out, int out_size)
{
    const float* query = (const float*)d_in[0];
    const float* key   = (const float*)d_in[1];
    const float* value = (const float*)d_in[2];
    const float* Wq    = (const float*)d_in[3];
    const float* bq    = (const float*)d_in[4];
    const float* Wk    = (const float*)d_in[5];
    const float* bk    = (const float*)d_in[6];
    const float* Wv    = (const float*)d_in[7];
    const float* bv    = (const float*)d_in[8];
    const float* Wo    = (const float*)d_in[9];
    const float* bo    = (const float*)d_in[10];
    float* out = (float*)d_out;

    __half *xqh, *xql, *xkh, *xkl, *xvh, *xvl;
    __half *wq, *wk, *wv, *wo;
    __half *qh, *ql, *k, *vt, *ah, *al;
    cudaGetSymbolAddress((void**)&xqh, g_xq_h);  cudaGetSymbolAddress((void**)&xql, g_xq_l);
    cudaGetSymbolAddress((void**)&xkh, g_xk_h);  cudaGetSymbolAddress((void**)&xkl, g_xk_l);
    cudaGetSymbolAddress((void**)&xvh, g_xv_h);  cudaGetSymbolAddress((void**)&xvl, g_xv_l);
    cudaGetSymbolAddress((void**)&wq, g_wq);     cudaGetSymbolAddress((void**)&wk, g_wk);
    cudaGetSymbolAddress((void**)&wv, g_wv);     cudaGetSymbolAddress((void**)&wo, g_wo);
    cudaGetSymbolAddress((void**)&qh, g_q_h);    cudaGetSymbolAddress((void**)&ql, g_q_l);
    cudaGetSymbolAddress((void**)&k,  g_k);      cudaGetSymbolAddress((void**)&vt, g_vt);
    cudaGetSymbolAddress((void**)&ah, g_a_h);    cudaGetSymbolAddress((void**)&al, g_a_l);

    cudaFuncSetAttribute(gemm_mma<0>, cudaFuncAttributeMaxDynamicSharedMemorySize, GSM_BYTES);
    cudaFuncSetAttribute(gemm_mma<1>, cudaFuncAttributeMaxDynamicSharedMemorySize, GSM_BYTES);
    cudaFuncSetAttribute(kv_proj,     cudaFuncAttributeMaxDynamicSharedMemorySize, GSM_BYTES);
    cudaFuncSetAttribute(flash_mma,   cudaFuncAttributeMaxDynamicSharedMemorySize, FL_SMEM);

    const float attn_scale = 0.08838834764831845f;  // 1/sqrt(128)

    // 1) input conversions (z = q/k/v) -> split fp16
    conv_all<<<dim3(NELEM_X / 1024, 3), 256>>>(query, key, value,
                                               xqh, xql, xkh, xkl, xvh, xvl);

    // 2) weight transposes -> single fp16
    convT_big<<<dim3(D_MODEL / 32, D_MODEL / 32, 2), 256>>>(Wq, Wo, wq, wo);
    convT_small<<<dim3(HEAD_DIM / 32, D_MODEL / 32, 2), 256>>>(Wk, Wv, wk, wv);

    // 3) Q projection (scaled by 1/sqrt(d), split fp16 output)
    gemm_mma<1><<<dim3(D_MODEL / 128, MROWS / 128), 256, GSM_BYTES>>>(
        xqh, xql, wq, bq, nullptr, qh, ql,
        D_MODEL, D_MODEL, D_MODEL, D_MODEL, attn_scale);

    // 4) K + V projections (z-fused; V stored transposed, both single fp16)
    kv_proj<<<dim3(1, MROWS / 128, 2), 256, GSM_BYTES>>>(
        xkh, xkl, xvh, xvl, wk, wv, bk, bv, k, vt);

    // 5) fused flash attention -> split-fp16 attn output
    flash_mma<<<dim3(SEQ / 128, NUM_HEADS, BATCH), 256, FL_SMEM>>>(
        qh, ql, k, vt, ah, al);

    // 6) output projection -> d_out (fp32 + bias)
    gemm_mma<0><<<dim3(D_MODEL / 128, MROWS / 128), 256, GSM_BYTES>>>(
        ah, al, wo, bo, out, nullptr, nullptr,
        D_MODEL, D_MODEL, D_MODEL, D_MODEL, 1.0f);
}

// round 12
// speedup vs baseline: 1.7185x; 1.2015x over previous
#include <cuda_runtime.h>
#include <cuda_fp16.h>
#include <math.h>
#include <stdint.h>

// ---------------- problem constants ----------------
#define D_MODEL   2048
#define NUM_HEADS 16
#define HEAD_DIM  128
#define BATCH     2
#define SEQ       2048
#define MROWS     (BATCH * SEQ)        // 4096

#define NELEM_X   (MROWS * D_MODEL)          // 8388608
#define NELEM_W   (D_MODEL * D_MODEL)        // 4194304
#define NELEM_WKV (D_MODEL * HEAD_DIM)       // 262144
#define NELEM_KV  (MROWS * HEAD_DIM)         // 524288

// ---------------- scratch (__device__ statics; no cudaMalloc) ----------
__device__ __align__(16) __half g_xq_h[NELEM_X], g_xq_l[NELEM_X];
__device__ __align__(16) __half g_xk_h[NELEM_X], g_xk_l[NELEM_X];
__device__ __align__(16) __half g_xv_h[NELEM_X], g_xv_l[NELEM_X];
__device__ __align__(16) __half g_wq[NELEM_W];        // [N,K] single fp16
__device__ __align__(16) __half g_wk[NELEM_WKV];
__device__ __align__(16) __half g_wv[NELEM_WKV];
__device__ __align__(16) __half g_wo[NELEM_W];
__device__ __align__(16) __half g_q[NELEM_X];                       // pre-scaled Q single
__device__ __align__(16) __half g_k[NELEM_KV];                      // K single [b*s, d]
__device__ __align__(16) __half g_vt[NELEM_KV];                     // V^T single [b][d, s]
__device__ __align__(16) __half g_a_h[NELEM_X], g_a_l[NELEM_X];     // attn out hi/lo

// ---------------- low-level helpers ----------
__device__ __forceinline__ uint32_t smem_to_u32(const void* p) {
    uint32_t a;
    asm("{ .reg .u64 t; cvta.to.shared.u64 t, %1; cvt.u32.u64 %0, t; }" : "=r"(a) : "l"(p));
    return a;
}
#define CP16(dst, src) \
    asm volatile("cp.async.cg.shared.global [%0], [%1], 16;" :: "r"(dst), "l"(src))
#define CP_COMMIT() asm volatile("cp.async.commit_group;" ::: "memory")
#define CP_WAIT(n)  asm volatile("cp.async.wait_group %0;" :: "n"(n) : "memory")

__device__ __forceinline__ void ldsm4(uint32_t* r, uint32_t addr) {
    asm volatile("ldmatrix.sync.aligned.m8n8.x4.shared.b16 {%0,%1,%2,%3}, [%4];"
        : "=r"(r[0]), "=r"(r[1]), "=r"(r[2]), "=r"(r[3]) : "r"(addr));
}
// fp16 inputs, fp32 accumulate
__device__ __forceinline__ void mma16816h(float* c, const uint32_t* a, const uint32_t* b) {
    asm volatile("mma.sync.aligned.m16n8k16.row.col.f32.f16.f16.f32 "
        "{%0,%1,%2,%3}, {%4,%5,%6,%7}, {%8,%9}, {%0,%1,%2,%3};"
        : "+f"(c[0]), "+f"(c[1]), "+f"(c[2]), "+f"(c[3])
        : "r"(a[0]), "r"(a[1]), "r"(a[2]), "r"(a[3]), "r"(b[0]), "r"(b[1]));
}

__device__ __forceinline__ void split2h(float t0, float t1, __half2& hi, __half2& lo) {
    __half h0 = __float2half(t0);
    __half h1 = __float2half(t1);
    hi = __halves2half2(h0, h1);
    lo = __halves2half2(__float2half(t0 - __half2float(h0)),
                        __float2half(t1 - __half2float(h1)));
}

// swizzled smem offset for (row r, 16B-chunk c) within a 64B-wide tile block
__device__ __forceinline__ uint32_t sw_off(int r, int c) {
    return (uint32_t)(r * 64 + ((c ^ ((r >> 1) & 3)) << 4));
}

// =====================================================================
// Conversion kernels
// =====================================================================
__global__ void __launch_bounds__(256)
conv_all(const float* __restrict__ q, const float* __restrict__ k,
         const float* __restrict__ v,
         __half* __restrict__ qh, __half* __restrict__ ql,
         __half* __restrict__ kh, __half* __restrict__ kl,
         __half* __restrict__ vh, __half* __restrict__ vl)
{
    const int z = blockIdx.y;
    const float* x = (z == 0) ? q : (z == 1) ? k : v;
    __half* h = (z == 0) ? qh : (z == 1) ? kh : vh;
    __half* l = (z == 0) ? ql : (z == 1) ? kl : vl;
    const int i = blockIdx.x * 256 + threadIdx.x;
    float4 val = ((const float4*)x)[i];
    __half2 h0, h1, l0, l1;
    split2h(val.x, val.y, h0, l0);
    split2h(val.z, val.w, h1, l1);
    ((__half2*)h)[i * 2]     = h0;
    ((__half2*)h)[i * 2 + 1] = h1;
    ((__half2*)l)[i * 2]     = l0;
    ((__half2*)l)[i * 2 + 1] = l1;
}

// W [K,N] row-major -> T [N,K] single fp16
__device__ __forceinline__ void convT_body(
    const float* __restrict__ W, __half* __restrict__ Th, int Kd, int Nd)
{
    __shared__ float t[32][33];
    const int n0 = blockIdx.x * 32, k0 = blockIdx.y * 32;
    const int tx = threadIdx.x & 31, ty = threadIdx.x >> 5;
#pragma unroll
    for (int i = 0; i < 4; i++)
        t[ty + i * 8][tx] = W[(size_t)(k0 + ty + i * 8) * Nd + n0 + tx];
    __syncthreads();
#pragma unroll
    for (int i = 0; i < 4; i++) {
        float v = t[tx][ty + i * 8];
        Th[(size_t)(n0 + ty + i * 8) * Kd + k0 + tx] = __float2half(v);
    }
}

__global__ void __launch_bounds__(256)
convT_big(const float* __restrict__ Wq, const float* __restrict__ Wo,
          __half* __restrict__ wq, __half* __restrict__ wo)
{
    if (blockIdx.z == 0) convT_body(Wq, wq, D_MODEL, D_MODEL);
    else                 convT_body(Wo, wo, D_MODEL, D_MODEL);
}

__global__ void __launch_bounds__(256)
convT_small(const float* __restrict__ Wk, const float* __restrict__ Wv,
            __half* __restrict__ wk, __half* __restrict__ wv)
{
    if (blockIdx.z == 0) convT_body(Wk, wk, D_MODEL, HEAD_DIM);
    else                 convT_body(Wv, wv, D_MODEL, HEAD_DIM);
}

// =====================================================================
// 2-term split-fp16 GEMM: C[M,N] = (Ah+Al)[M,K] @ B[N,K]^T (+bias)(*scale)
// CTA 128x128, BK=32, 3-stage cp.async, 8 warps (64x32 warp tile).
// EPI: 0 = fp32+bias, 1 = fp16 hi/lo (+bias,*scale),
//      2 = fp16 single (+bias, *scale), 3 = fp16 single transposed V^T (+bias).
// =====================================================================
#define STAGES     3
#define STAGE_B    24576                      // Ah 8K | Al 8K | Bh 8K
#define GSM_BYTES  (STAGES * STAGE_B)         // 73728 -> 2 CTAs/SM

template<int EPI>
__device__ __forceinline__ void gemm_body(
         const __half* __restrict__ Ah, const __half* __restrict__ Al,
         const __half* __restrict__ Bh,
         const float* __restrict__ bias,
         float* __restrict__ Cf, __half* __restrict__ Ch, __half* __restrict__ Cl,
         int K, int lda, int ldb, int ldc, float scale)
{
    extern __shared__ char smem[];
    const uint32_t sb = smem_to_u32(smem);
    const int tid = threadIdx.x, lane = tid & 31, wid = tid >> 5;
    const int wm = wid & 1, wn = wid >> 1;
    const int row0 = blockIdx.y * 128, col0 = blockIdx.x * 128;

    const char* pAh = (const char*)(Ah + (size_t)row0 * lda);
    const char* pAl = (const char*)(Al + (size_t)row0 * lda);
    const char* pBh = (const char*)(Bh + (size_t)col0 * ldb);
    const size_t lda2 = (size_t)lda * 2, ldb2 = (size_t)ldb * 2;

    const int r0c = tid >> 2,            c0c = tid & 3;
    const int r1c = (tid + 256) >> 2,    c1c = (tid + 256) & 3;
    const uint32_t so0 = sw_off(r0c, c0c), so1 = sw_off(r1c, c1c);

    float acc[4][4][4];
#pragma unroll
    for (int a = 0; a < 4; a++)
#pragma unroll
        for (int b = 0; b < 4; b++)
#pragma unroll
            for (int c = 0; c < 4; c++) acc[a][b][c] = 0.0f;

    const int niter = K >> 5;

#define LOAD_STAGE(s, kof) do {                                              \
        const uint32_t bA = sb + (s) * STAGE_B;                              \
        const size_t kb = (size_t)(kof) * 2;                                 \
        CP16(bA + so0,         pAh + r0c * lda2 + kb + c0c * 16);            \
        CP16(bA + so1,         pAh + r1c * lda2 + kb + c1c * 16);            \
        CP16(bA + 8192 + so0,  pAl + r0c * lda2 + kb + c0c * 16);            \
        CP16(bA + 8192 + so1,  pAl + r1c * lda2 + kb + c1c * 16);            \
        CP16(bA + 16384 + so0, pBh + r0c * ldb2 + kb + c0c * 16);            \
        CP16(bA + 16384 + so1, pBh + r1c * ldb2 + kb + c1c * 16);            \
    } while (0)

    LOAD_STAGE(0, 0);  CP_COMMIT();
    LOAD_STAGE(1, 32); CP_COMMIT();

    for (int i = 0; i < niter; i++) {
        if (i < niter - 1) { CP_WAIT(1); } else { CP_WAIT(0); }
        __syncthreads();
        if (i + 2 < niter) { LOAD_STAGE((i + 2) % STAGES, (i + 2) * 32); CP_COMMIT(); }

        const uint32_t sA = sb + (i % STAGES) * STAGE_B;
        const uint32_t sB = sA + 16384;
#pragma unroll
        for (int h = 0; h < 2; h++) {
            uint32_t ah[4][4], al[4][4], bh[2][4];
            const int chk = 2 * h + (lane >> 4);
#pragma unroll
            for (int mt = 0; mt < 4; mt++) {
                const int r = wm * 64 + mt * 16 + (lane & 15);
                const uint32_t off = sw_off(r, chk);
                ldsm4(ah[mt], sA + off);
                ldsm4(al[mt], sA + 8192 + off);
            }
#pragma unroll
            for (int np = 0; np < 2; np++) {
                const int r = wn * 32 + np * 16 + (lane & 15);
                ldsm4(bh[np], sB + sw_off(r, chk));
            }
#pragma unroll
            for (int mt = 0; mt < 4; mt++)
#pragma unroll
                for (int nt = 0; nt < 4; nt++) {
                    const int np = nt >> 1, sel = nt & 1;
                    uint32_t bf[2] = { bh[np][sel], bh[np][sel + 2] };
                    mma16816h(acc[mt][nt], ah[mt], bf);
                    mma16816h(acc[mt][nt], al[mt], bf);
                }
        }
    }
#undef LOAD_STAGE

    // ---------------- epilogue ----------------
#pragma unroll
    for (int mt = 0; mt < 4; mt++) {
#pragma unroll
        for (int nt = 0; nt < 4; nt++) {
            const float* a = acc[mt][nt];
            const int gr = row0 + wm * 64 + mt * 16 + (lane >> 2);
            const int gc = col0 + wn * 32 + nt * 8 + (lane & 3) * 2;
            if (EPI == 0) {
                float b0 = bias[gc], b1 = bias[gc + 1];
                float2 v0 = { a[0] + b0, a[1] + b1 };
                float2 v1 = { a[2] + b0, a[3] + b1 };
                *(float2*)&Cf[(size_t)gr * ldc + gc]       = v0;
                *(float2*)&Cf[(size_t)(gr + 8) * ldc + gc] = v1;
            } else if (EPI == 1) {
                const float b0 = bias[gc], b1 = bias[gc + 1];
                __half2 hh, ll;
                split2h((a[0] + b0) * scale, (a[1] + b1) * scale, hh, ll);
                size_t o = (size_t)gr * ldc + gc;
                *(__half2*)&Ch[o] = hh;
                *(__half2*)&Cl[o] = ll;
                split2h((a[2] + b0) * scale, (a[3] + b1) * scale, hh, ll);
                o = (size_t)(gr + 8) * ldc + gc;
                *(__half2*)&Ch[o] = hh;
                *(__half2*)&Cl[o] = ll;
            } else if (EPI == 2) {
                const float b0 = bias[gc], b1 = bias[gc + 1];
                size_t o = (size_t)gr * ldc + gc;
                *(__half2*)&Ch[o] = __halves2half2(__float2half((a[0] + b0) * scale),
                                                   __float2half((a[1] + b1) * scale));
                o = (size_t)(gr + 8) * ldc + gc;
                *(__half2*)&Ch[o] = __halves2half2(__float2half((a[2] + b0) * scale),
                                                   __float2half((a[3] + b1) * scale));
            } else {  // EPI == 3: V^T single store: out[b][dim][token]
#pragma unroll
                for (int q = 0; q < 4; q++) {
                    const int rr = gr + (q >> 1) * 8;
                    const int cc = gc + (q & 1);
                    const float t = a[q] + bias[cc];
                    const size_t o = (size_t)(rr >> 11) * ((size_t)HEAD_DIM * SEQ)
                                   + (size_t)cc * SEQ + (rr & (SEQ - 1));
                    Ch[o] = __float2half(t);
                }
            }
        }
    }
}

template<int EPI>
__global__ void __launch_bounds__(256, 2)
gemm_mma(const __half* __restrict__ Ah, const __half* __restrict__ Al,
         const __half* __restrict__ Bh, const float* __restrict__ bias,
         float* __restrict__ Cf, __half* __restrict__ Ch, __half* __restrict__ Cl,
         int K, int lda, int ldb, int ldc, float scale)
{
    gemm_body<EPI>(Ah, Al, Bh, bias, Cf, Ch, Cl, K, lda, ldb, ldc, scale);
}

// K and V projections z-fused (z=0: K single store, z=1: V^T single store)
__global__ void __launch_bounds__(256, 2)
kv_proj(const __half* __restrict__ xkh, const __half* __restrict__ xkl,
        const __half* __restrict__ xvh, const __half* __restrict__ xvl,
        const __half* __restrict__ wk, const __half* __restrict__ wv,
        const float* __restrict__ bk, const float* __restrict__ bv,
        __half* __restrict__ k, __half* __restrict__ vt)
{
    if (blockIdx.z == 0)
        gemm_body<2>(xkh, xkl, wk, bk, nullptr, k, nullptr,
                     D_MODEL, D_MODEL, D_MODEL, HEAD_DIM, 1.0f);
    else
        gemm_body<3>(xvh, xvl, wv, bv, nullptr, vt, nullptr,
                     D_MODEL, D_MODEL, D_MODEL, 0, 1.0f);
}

// =====================================================================
// Fused flash attention (pure single-fp16 tensor ops, online softmax).
// CTA: 128 q rows x full KV sweep. 8 warps x 16 rows. KT=64 per iter.
// Q (pre-scaled) single fp16, K single, V^T single, P single.
// smem: 2 stages x 32KB (K 16K | Vt 16K) + Q 32KB @65536 = 96KB.
// Output: split fp16 hi/lo (feeds split-A O-projection).
// =====================================================================
#define FL_STAGE  32768
#define FL_Q      65536
#define FL_SMEM   98304

__global__ void __launch_bounds__(256)
flash_mma(const __half* __restrict__ Qg,
          const __half* __restrict__ Kg, const __half* __restrict__ Vtg,
          __half* __restrict__ Oh, __half* __restrict__ Ol)
{
    extern __shared__ char smem[];
    const uint32_t sb = smem_to_u32(smem);
    const int tid = threadIdx.x, lane = tid & 31, w = tid >> 5;
    const int q0 = blockIdx.x * 128;
    const int hh = blockIdx.y;
    const int b  = blockIdx.z;

    const char* pQ = (const char*)(Qg + ((size_t)(b * SEQ) + q0) * D_MODEL + hh * HEAD_DIM);
    const char* pK = (const char*)(Kg + (size_t)b * SEQ * HEAD_DIM);
    const char* pV = (const char*)(Vtg + (size_t)b * HEAD_DIM * SEQ);

#define LOAD_KV(stg, kv0) do {                                               \
        const uint32_t bb = sb + (uint32_t)(stg) * FL_STAGE;                 \
        _Pragma("unroll")                                                    \
        for (int i2 = 0; i2 < 4; i2++) {                                     \
            const int idx = tid + i2 * 256;                                  \
            const int r = idx >> 4, c = idx & 15;                            \
            const uint32_t d = bb + ((c >> 2) << 12) + sw_off(r, c & 3);     \
            const size_t so = (size_t)((kv0) + r) * 256 + (c & 3) * 16 + (c >> 2) * 64; \
            CP16(d, pK + so);                                                \
        }                                                                    \
        _Pragma("unroll")                                                    \
        for (int i2 = 0; i2 < 4; i2++) {                                     \
            const int idx = tid + i2 * 256;                                  \
            const int r = idx >> 3, c = idx & 7;                             \
            const uint32_t d = bb + 16384 + ((c >> 2) << 13) + sw_off(r, c & 3); \
            const size_t so = (size_t)r * (SEQ * 2) + (size_t)(kv0) * 2 + (c & 3) * 16 + (c >> 2) * 64; \
            CP16(d, pV + so);                                                \
        }                                                                    \
    } while (0)

    // stage Q once (single fp16, 32KB)
#pragma unroll
    for (int i2 = 0; i2 < 8; i2++) {
        const int idx = tid + i2 * 256;
        const int r = idx >> 4, c = idx & 15;
        const uint32_t d = sb + FL_Q + ((c >> 2) << 13) + sw_off(r, c & 3);
        const size_t so = (size_t)r * (D_MODEL * 2) + (c & 3) * 16 + (c >> 2) * 64;
        CP16(d, pQ + so);
    }
    CP_COMMIT();
    LOAD_KV(0, 0);
    CP_COMMIT();

    CP_WAIT(1);
    __syncthreads();

    // Q fragments: 8 k-steps
    uint32_t qf[8][4];
#pragma unroll
    for (int ks = 0; ks < 8; ks++) {
        const int blk = ks >> 1;
        const int c   = (ks & 1) * 2 + (lane >> 4);
        const int r   = w * 16 + (lane & 15);
        ldsm4(qf[ks], sb + FL_Q + (blk << 13) + sw_off(r, c));
    }

    float oacc[16][4];
#pragma unroll
    for (int nt = 0; nt < 16; nt++)
#pragma unroll
        for (int q = 0; q < 4; q++) oacc[nt][q] = 0.0f;
    float m0 = -1e30f, m1 = -1e30f, l0 = 0.0f, l1 = 0.0f;

    for (int it = 0; it < SEQ / 64; it++) {
        CP_WAIT(0);
        __syncthreads();
        if (it + 1 < SEQ / 64) { LOAD_KV((it + 1) & 1, (it + 1) * 64); CP_COMMIT(); }

        const uint32_t kb = sb + (uint32_t)(it & 1) * FL_STAGE;
        const uint32_t vb = kb + 16384;

        // -------- scores: S[16q x 64kv] = Q K^T --------
        float sacc[8][4];
#pragma unroll
        for (int nt = 0; nt < 8; nt++)
#pragma unroll
            for (int q = 0; q < 4; q++) sacc[nt][q] = 0.0f;

#pragma unroll
        for (int ks = 0; ks < 8; ks++) {
            const int blk = ks >> 1;
            const int cc  = (ks & 1) * 2 + (lane >> 4);
#pragma unroll
            for (int g = 0; g < 4; g++) {
                uint32_t kh4[4];
                const int r = g * 16 + (lane & 15);
                ldsm4(kh4, kb + (blk << 12) + sw_off(r, cc));
#pragma unroll
                for (int sel = 0; sel < 2; sel++) {
                    uint32_t f[2] = { kh4[sel], kh4[sel + 2] };
                    mma16816h(sacc[g * 2 + sel], qf[ks], f);
                }
            }
        }

        // -------- online softmax --------
        float mx0 = sacc[0][0], mx1 = sacc[0][2];
#pragma unroll
        for (int nt = 0; nt < 8; nt++) {
            mx0 = fmaxf(mx0, fmaxf(sacc[nt][0], sacc[nt][1]));
            mx1 = fmaxf(mx1, fmaxf(sacc[nt][2], sacc[nt][3]));
        }
        mx0 = fmaxf(mx0, __shfl_xor_sync(0xffffffffu, mx0, 1));
        mx0 = fmaxf(mx0, __shfl_xor_sync(0xffffffffu, mx0, 2));
        mx1 = fmaxf(mx1, __shfl_xor_sync(0xffffffffu, mx1, 1));
        mx1 = fmaxf(mx1, __shfl_xor_sync(0xffffffffu, mx1, 2));
        const float mn0 = fmaxf(m0, mx0), mn1 = fmaxf(m1, mx1);
        const float cr0 = __expf(m0 - mn0), cr1 = __expf(m1 - mn1);
        m0 = mn0; m1 = mn1;

        float s0 = 0.0f, s1 = 0.0f;
        uint32_t pp[8][2];
#pragma unroll
        for (int nt = 0; nt < 8; nt++) {
            const float p0 = __expf(sacc[nt][0] - mn0);
            const float p1 = __expf(sacc[nt][1] - mn0);
            const float p2 = __expf(sacc[nt][2] - mn1);
            const float p3 = __expf(sacc[nt][3] - mn1);
            s0 += p0 + p1;
            s1 += p2 + p3;
            __half2 x0 = __floats2half2_rn(p0, p1);
            __half2 x1 = __floats2half2_rn(p2, p3);
            pp[nt][0] = *(uint32_t*)&x0;
            pp[nt][1] = *(uint32_t*)&x1;
        }
        s0 += __shfl_xor_sync(0xffffffffu, s0, 1);
        s0 += __shfl_xor_sync(0xffffffffu, s0, 2);
        s1 += __shfl_xor_sync(0xffffffffu, s1, 1);
        s1 += __shfl_xor_sync(0xffffffffu, s1, 2);
        l0 = l0 * cr0 + s0;
        l1 = l1 * cr1 + s1;

#pragma unroll
        for (int nt = 0; nt < 16; nt++) {
            oacc[nt][0] *= cr0; oacc[nt][1] *= cr0;
            oacc[nt][2] *= cr1; oacc[nt][3] *= cr1;
        }

        // -------- PV: out += P[16x64] V[64x128] --------
#pragma unroll
        for (int kk = 0; kk < 4; kk++) {
            uint32_t ap[4] = { pp[2 * kk][0], pp[2 * kk][1],
                               pp[2 * kk + 1][0], pp[2 * kk + 1][1] };
            const int blk = kk >> 1;
            const int cc  = (kk & 1) * 2 + (lane >> 4);
#pragma unroll
            for (int g = 0; g < 8; g++) {
                uint32_t vh4[4];
                const int r = g * 16 + (lane & 15);
                ldsm4(vh4, vb + (blk << 13) + sw_off(r, cc));
#pragma unroll
                for (int sel = 0; sel < 2; sel++) {
                    uint32_t f[2] = { vh4[sel], vh4[sel + 2] };
                    mma16816h(oacc[g * 2 + sel], ap, f);
                }
            }
        }
    }
#undef LOAD_KV

    // -------- epilogue: normalize + split-fp16 store --------
    const float i0 = 1.0f / l0, i1 = 1.0f / l1;
    const size_t ro0 = ((size_t)(b * SEQ) + q0 + w * 16 + (lane >> 2)) * D_MODEL
                     + (size_t)hh * HEAD_DIM;
    const size_t ro1 = ro0 + (size_t)8 * D_MODEL;
#pragma unroll
    for (int nt = 0; nt < 16; nt++) {
        const int col = nt * 8 + (lane & 3) * 2;
        __half2 hx, lx;
        split2h(oacc[nt][0] * i0, oacc[nt][1] * i0, hx, lx);
        *(__half2*)&Oh[ro0 + col] = hx;
        *(__half2*)&Ol[ro0 + col] = lx;
        split2h(oacc[nt][2] * i1, oacc[nt][3] * i1, hx, lx);
        *(__half2*)&Oh[ro1 + col] = hx;
        *(__half2*)&Ol[ro1 + col] = lx;
    }
}

// =====================================================================
// launch
// =====================================================================
extern "C" void kernel_launch(void* const* d_in, const int* in_sizes, int n_in,
                              void* d_out, int out_size)
{
    const float* query = (const float*)d_in[0];
    const float* key   = (const float*)d_in[1];
    const float* value = (const float*)d_in[2];
    const float* Wq    = (const float*)d_in[3];
    const float* bq    = (const float*)d_in[4];
    const float* Wk    = (const float*)d_in[5];
    const float* bk    = (const float*)d_in[6];
    const float* Wv    = (const float*)d_in[7];
    const float* bv    = (const float*)d_in[8];
    const float* Wo    = (const float*)d_in[9];
    const float* bo    = (const float*)d_in[10];
    float* out = (float*)d_out;

    __half *xqh, *xql, *xkh, *xkl, *xvh, *xvl;
    __half *wq, *wk, *wv, *wo;
    __half *q, *k, *vt, *ah, *al;
    cudaGetSymbolAddress((void**)&xqh, g_xq_h);  cudaGetSymbolAddress((void**)&xql, g_xq_l);
    cudaGetSymbolAddress((void**)&xkh, g_xk_h);  cudaGetSymbolAddress((void**)&xkl, g_xk_l);
    cudaGetSymbolAddress((void**)&xvh, g_xv_h);  cudaGetSymbolAddress((void**)&xvl, g_xv_l);
    cudaGetSymbolAddress((void**)&wq, g_wq);     cudaGetSymbolAddress((void**)&wk, g_wk);
    cudaGetSymbolAddress((void**)&wv, g_wv);     cudaGetSymbolAddress((void**)&wo, g_wo);
    cudaGetSymbolAddress((void**)&q,  g_q);
    cudaGetSymbolAddress((void**)&k,  g_k);      cudaGetSymbolAddress((void**)&vt, g_vt);
    cudaGetSymbolAddress((void**)&ah, g_a_h);    cudaGetSymbolAddress((void**)&al, g_a_l);

    cudaFuncSetAttribute(gemm_mma<0>, cudaFuncAttributeMaxDynamicSharedMemorySize, GSM_BYTES);
    cudaFuncSetAttribute(gemm_mma<2>, cudaFuncAttributeMaxDynamicSharedMemorySize, GSM_BYTES);
    cudaFuncSetAttribute(kv_proj,     cudaFuncAttributeMaxDynamicSharedMemorySize, GSM_BYTES);
    cudaFuncSetAttribute(flash_mma,   cudaFuncAttributeMaxDynamicSharedMemorySize, FL_SMEM);

    const float attn_scale = 0.08838834764831845f;  // 1/sqrt(128)

    // 1) input conversions (z = q/k/v) -> split fp16
    conv_all<<<dim3(NELEM_X / 1024, 3), 256>>>(query, key, value,
                                               xqh, xql, xkh, xkl, xvh, xvl);

    // 2) weight transposes -> single fp16
    convT_big<<<dim3(D_MODEL / 32, D_MODEL / 32, 2), 256>>>(Wq, Wo, wq, wo);
    convT_small<<<dim3(HEAD_DIM / 32, D_MODEL / 32, 2), 256>>>(Wk, Wv, wk, wv);

    // 3) Q projection (scaled by 1/sqrt(d), SINGLE fp16 output)
    gemm_mma<2><<<dim3(D_MODEL / 128, MROWS / 128), 256, GSM_BYTES>>>(
        xqh, xql, wq, bq, nullptr, q, nullptr,
        D_MODEL, D_MODEL, D_MODEL, D_MODEL, attn_scale);

    // 4) K + V projections (z-fused; V stored transposed, both single fp16)
    kv_proj<<<dim3(1, MROWS / 128, 2), 256, GSM_BYTES>>>(
        xkh, xkl, xvh, xvl, wk, wv, bk, bv, k, vt);

    // 5) fused flash attention (single-fp16) -> split-fp16 attn output
    flash_mma<<<dim3(SEQ / 128, NUM_HEADS, BATCH), 256, FL_SMEM>>>(
        q, k, vt, ah, al);

    // 6) output projection (split-A) -> d_out (fp32 + bias)
    gemm_mma<0><<<dim3(D_MODEL / 128, MROWS / 128), 256, GSM_BYTES>>>(
        ah, al, wo, bo, out, nullptr, nullptr,
        D_MODEL, D_MODEL, D_MODEL, D_MODEL, 1.0f);
}

// round 13
// speedup vs baseline: 2.3161x; 1.3477x over previous
#include <cuda_runtime.h>
#include <cuda_fp16.h>
#include <math.h>
#include <stdint.h>

// ---------------- problem constants ----------------
#define D_MODEL   2048
#define NUM_HEADS 16
#define HEAD_DIM  128
#define BATCH     2
#define SEQ       2048
#define MROWS     (BATCH * SEQ)        // 4096

#define NELEM_X   (MROWS * D_MODEL)          // 8388608
#define NELEM_W   (D_MODEL * D_MODEL)        // 4194304
#define NELEM_WKV (D_MODEL * HEAD_DIM)       // 262144
#define NELEM_KV  (MROWS * HEAD_DIM)         // 524288

// ---------------- scratch (__device__ statics; no cudaMalloc) ----------
__device__ __align__(16) __half g_xq[NELEM_X];                      // query single
__device__ __align__(16) __half g_xk_h[NELEM_X], g_xk_l[NELEM_X];   // key split
__device__ __align__(16) __half g_xv_h[NELEM_X], g_xv_l[NELEM_X];   // value split
__device__ __align__(16) __half g_wq[NELEM_W];        // [N,K] single fp16
__device__ __align__(16) __half g_wk[NELEM_WKV];
__device__ __align__(16) __half g_wv[NELEM_WKV];
__device__ __align__(16) __half g_wo[NELEM_W];
__device__ __align__(16) __half g_q[NELEM_X];                       // pre-scaled Q single
__device__ __align__(16) __half g_k[NELEM_KV];                      // K single [b*s, d]
__device__ __align__(16) __half g_vt[NELEM_KV];                     // V^T single [b][d, s]
__device__ __align__(16) __half g_a[NELEM_X];                       // attn out single

// ---------------- low-level helpers ----------
__device__ __forceinline__ uint32_t smem_to_u32(const void* p) {
    uint32_t a;
    asm("{ .reg .u64 t; cvta.to.shared.u64 t, %1; cvt.u32.u64 %0, t; }" : "=r"(a) : "l"(p));
    return a;
}
#define CP16(dst, src) \
    asm volatile("cp.async.cg.shared.global [%0], [%1], 16;" :: "r"(dst), "l"(src))
#define CP_COMMIT() asm volatile("cp.async.commit_group;" ::: "memory")
#define CP_WAIT(n)  asm volatile("cp.async.wait_group %0;" :: "n"(n) : "memory")

__device__ __forceinline__ void ldsm4(uint32_t* r, uint32_t addr) {
    asm volatile("ldmatrix.sync.aligned.m8n8.x4.shared.b16 {%0,%1,%2,%3}, [%4];"
        : "=r"(r[0]), "=r"(r[1]), "=r"(r[2]), "=r"(r[3]) : "r"(addr));
}
// fp16 inputs, fp32 accumulate
__device__ __forceinline__ void mma16816h(float* c, const uint32_t* a, const uint32_t* b) {
    asm volatile("mma.sync.aligned.m16n8k16.row.col.f32.f16.f16.f32 "
        "{%0,%1,%2,%3}, {%4,%5,%6,%7}, {%8,%9}, {%0,%1,%2,%3};"
        : "+f"(c[0]), "+f"(c[1]), "+f"(c[2]), "+f"(c[3])
        : "r"(a[0]), "r"(a[1]), "r"(a[2]), "r"(a[3]), "r"(b[0]), "r"(b[1]));
}

__device__ __forceinline__ void split2h(float t0, float t1, __half2& hi, __half2& lo) {
    __half h0 = __float2half(t0);
    __half h1 = __float2half(t1);
    hi = __halves2half2(h0, h1);
    lo = __halves2half2(__float2half(t0 - __half2float(h0)),
                        __float2half(t1 - __half2float(h1)));
}

// swizzled smem offset for (row r, 16B-chunk c) within a 64B-wide tile block
__device__ __forceinline__ uint32_t sw_off(int r, int c) {
    return (uint32_t)(r * 64 + ((c ^ ((r >> 1) & 3)) << 4));
}

// =====================================================================
// Conversion kernels
// z=0: query -> single fp16.  z=1: key -> split.  z=2: value -> split.
// =====================================================================
__global__ void __launch_bounds__(256)
conv_all(const float* __restrict__ q, const float* __restrict__ k,
         const float* __restrict__ v,
         __half* __restrict__ qs,
         __half* __restrict__ kh, __half* __restrict__ kl,
         __half* __restrict__ vh, __half* __restrict__ vl)
{
    const int z = blockIdx.y;
    const int i = blockIdx.x * 256 + threadIdx.x;
    if (z == 0) {
        float4 val = ((const float4*)q)[i];
        ((__half2*)qs)[i * 2]     = __floats2half2_rn(val.x, val.y);
        ((__half2*)qs)[i * 2 + 1] = __floats2half2_rn(val.z, val.w);
        return;
    }
    const float* x = (z == 1) ? k : v;
    __half* h = (z == 1) ? kh : vh;
    __half* l = (z == 1) ? kl : vl;
    float4 val = ((const float4*)x)[i];
    __half2 h0, h1, l0, l1;
    split2h(val.x, val.y, h0, l0);
    split2h(val.z, val.w, h1, l1);
    ((__half2*)h)[i * 2]     = h0;
    ((__half2*)h)[i * 2 + 1] = h1;
    ((__half2*)l)[i * 2]     = l0;
    ((__half2*)l)[i * 2 + 1] = l1;
}

// W [K,N] row-major -> T [N,K] single fp16
__device__ __forceinline__ void convT_body(
    const float* __restrict__ W, __half* __restrict__ Th, int Kd, int Nd)
{
    __shared__ float t[32][33];
    const int n0 = blockIdx.x * 32, k0 = blockIdx.y * 32;
    const int tx = threadIdx.x & 31, ty = threadIdx.x >> 5;
#pragma unroll
    for (int i = 0; i < 4; i++)
        t[ty + i * 8][tx] = W[(size_t)(k0 + ty + i * 8) * Nd + n0 + tx];
    __syncthreads();
#pragma unroll
    for (int i = 0; i < 4; i++) {
        float v = t[tx][ty + i * 8];
        Th[(size_t)(n0 + ty + i * 8) * Kd + k0 + tx] = __float2half(v);
    }
}

__global__ void __launch_bounds__(256)
convT_big(const float* __restrict__ Wq, const float* __restrict__ Wo,
          __half* __restrict__ wq, __half* __restrict__ wo)
{
    if (blockIdx.z == 0) convT_body(Wq, wq, D_MODEL, D_MODEL);
    else                 convT_body(Wo, wo, D_MODEL, D_MODEL);
}

__global__ void __launch_bounds__(256)
convT_small(const float* __restrict__ Wk, const float* __restrict__ Wv,
            __half* __restrict__ wk, __half* __restrict__ wv)
{
    if (blockIdx.z == 0) convT_body(Wk, wk, D_MODEL, HEAD_DIM);
    else                 convT_body(Wv, wv, D_MODEL, HEAD_DIM);
}

// =====================================================================
// SINGLE-fp16 GEMM: C[M,N] = A[M,K] @ B[N,K]^T (+bias)(*scale)
// CTA 128x128, BK=32, 3-stage cp.async, 8 warps (64x32 warp tile).
// EPI: 0 = fp32+bias, 2 = fp16 single (+bias, *scale).
// =====================================================================
#define SSTAGE_B   16384                      // A 8K | B 8K
#define SSM_BYTES  (3 * SSTAGE_B)             // 49152 -> 2+ CTAs/SM

template<int EPI>
__global__ void __launch_bounds__(256, 2)
gemm_single(const __half* __restrict__ A, const __half* __restrict__ B,
            const float* __restrict__ bias,
            float* __restrict__ Cf, __half* __restrict__ Ch,
            int K, int lda, int ldb, int ldc, float scale)
{
    extern __shared__ char smem[];
    const uint32_t sb = smem_to_u32(smem);
    const int tid = threadIdx.x, lane = tid & 31, wid = tid >> 5;
    const int wm = wid & 1, wn = wid >> 1;
    const int row0 = blockIdx.y * 128, col0 = blockIdx.x * 128;

    const char* pA = (const char*)(A + (size_t)row0 * lda);
    const char* pB = (const char*)(B + (size_t)col0 * ldb);
    const size_t lda2 = (size_t)lda * 2, ldb2 = (size_t)ldb * 2;

    const int r0c = tid >> 2,            c0c = tid & 3;
    const int r1c = (tid + 256) >> 2,    c1c = (tid + 256) & 3;
    const uint32_t so0 = sw_off(r0c, c0c), so1 = sw_off(r1c, c1c);

    float acc[4][4][4];
#pragma unroll
    for (int a = 0; a < 4; a++)
#pragma unroll
        for (int b = 0; b < 4; b++)
#pragma unroll
            for (int c = 0; c < 4; c++) acc[a][b][c] = 0.0f;

    const int niter = K >> 5;

#define LOAD_S(s, kof) do {                                                  \
        const uint32_t bA = sb + (s) * SSTAGE_B;                             \
        const size_t kb = (size_t)(kof) * 2;                                 \
        CP16(bA + so0,        pA + r0c * lda2 + kb + c0c * 16);              \
        CP16(bA + so1,        pA + r1c * lda2 + kb + c1c * 16);              \
        CP16(bA + 8192 + so0, pB + r0c * ldb2 + kb + c0c * 16);              \
        CP16(bA + 8192 + so1, pB + r1c * ldb2 + kb + c1c * 16);              \
    } while (0)

    LOAD_S(0, 0);  CP_COMMIT();
    LOAD_S(1, 32); CP_COMMIT();

    for (int i = 0; i < niter; i++) {
        if (i < niter - 1) { CP_WAIT(1); } else { CP_WAIT(0); }
        __syncthreads();
        if (i + 2 < niter) { LOAD_S((i + 2) % 3, (i + 2) * 32); CP_COMMIT(); }

        const uint32_t sA = sb + (i % 3) * SSTAGE_B;
        const uint32_t sB = sA + 8192;
#pragma unroll
        for (int h = 0; h < 2; h++) {
            uint32_t ah[4][4], bh[2][4];
            const int chk = 2 * h + (lane >> 4);
#pragma unroll
            for (int mt = 0; mt < 4; mt++) {
                const int r = wm * 64 + mt * 16 + (lane & 15);
                ldsm4(ah[mt], sA + sw_off(r, chk));
            }
#pragma unroll
            for (int np = 0; np < 2; np++) {
                const int r = wn * 32 + np * 16 + (lane & 15);
                ldsm4(bh[np], sB + sw_off(r, chk));
            }
#pragma unroll
            for (int mt = 0; mt < 4; mt++)
#pragma unroll
                for (int nt = 0; nt < 4; nt++) {
                    const int np = nt >> 1, sel = nt & 1;
                    uint32_t bf[2] = { bh[np][sel], bh[np][sel + 2] };
                    mma16816h(acc[mt][nt], ah[mt], bf);
                }
        }
    }
#undef LOAD_S

    // ---------------- epilogue ----------------
#pragma unroll
    for (int mt = 0; mt < 4; mt++) {
#pragma unroll
        for (int nt = 0; nt < 4; nt++) {
            const float* a = acc[mt][nt];
            const int gr = row0 + wm * 64 + mt * 16 + (lane >> 2);
            const int gc = col0 + wn * 32 + nt * 8 + (lane & 3) * 2;
            if (EPI == 0) {
                float b0 = bias[gc], b1 = bias[gc + 1];
                float2 v0 = { a[0] + b0, a[1] + b1 };
                float2 v1 = { a[2] + b0, a[3] + b1 };
                *(float2*)&Cf[(size_t)gr * ldc + gc]       = v0;
                *(float2*)&Cf[(size_t)(gr + 8) * ldc + gc] = v1;
            } else {
                const float b0 = bias[gc], b1 = bias[gc + 1];
                size_t o = (size_t)gr * ldc + gc;
                *(__half2*)&Ch[o] = __halves2half2(__float2half((a[0] + b0) * scale),
                                                   __float2half((a[1] + b1) * scale));
                o = (size_t)(gr + 8) * ldc + gc;
                *(__half2*)&Ch[o] = __halves2half2(__float2half((a[2] + b0) * scale),
                                                   __float2half((a[3] + b1) * scale));
            }
        }
    }
}

// =====================================================================
// 2-term split-fp16 GEMM body for K/V projections (A split, B single).
// CTA 128x128, BK=32, 3-stage. EPI: 2 = fp16 single (+bias),
// 3 = fp16 single transposed V^T (+bias).
// =====================================================================
#define STAGE_B    24576                      // Ah 8K | Al 8K | Bh 8K
#define GSM_BYTES  (3 * STAGE_B)              // 73728

template<int EPI>
__device__ __forceinline__ void gemm_body(
         const __half* __restrict__ Ah, const __half* __restrict__ Al,
         const __half* __restrict__ Bh,
         const float* __restrict__ bias,
         __half* __restrict__ Ch,
         int K, int lda, int ldb, int ldc)
{
    extern __shared__ char smem[];
    const uint32_t sb = smem_to_u32(smem);
    const int tid = threadIdx.x, lane = tid & 31, wid = tid >> 5;
    const int wm = wid & 1, wn = wid >> 1;
    const int row0 = blockIdx.y * 128, col0 = blockIdx.x * 128;

    const char* pAh = (const char*)(Ah + (size_t)row0 * lda);
    const char* pAl = (const char*)(Al + (size_t)row0 * lda);
    const char* pBh = (const char*)(Bh + (size_t)col0 * ldb);
    const size_t lda2 = (size_t)lda * 2, ldb2 = (size_t)ldb * 2;

    const int r0c = tid >> 2,            c0c = tid & 3;
    const int r1c = (tid + 256) >> 2,    c1c = (tid + 256) & 3;
    const uint32_t so0 = sw_off(r0c, c0c), so1 = sw_off(r1c, c1c);

    float acc[4][4][4];
#pragma unroll
    for (int a = 0; a < 4; a++)
#pragma unroll
        for (int b = 0; b < 4; b++)
#pragma unroll
            for (int c = 0; c < 4; c++) acc[a][b][c] = 0.0f;

    const int niter = K >> 5;

#define LOAD_STAGE(s, kof) do {                                              \
        const uint32_t bA = sb + (s) * STAGE_B;                              \
        const size_t kb = (size_t)(kof) * 2;                                 \
        CP16(bA + so0,         pAh + r0c * lda2 + kb + c0c * 16);            \
        CP16(bA + so1,         pAh + r1c * lda2 + kb + c1c * 16);            \
        CP16(bA + 8192 + so0,  pAl + r0c * lda2 + kb + c0c * 16);            \
        CP16(bA + 8192 + so1,  pAl + r1c * lda2 + kb + c1c * 16);            \
        CP16(bA + 16384 + so0, pBh + r0c * ldb2 + kb + c0c * 16);            \
        CP16(bA + 16384 + so1, pBh + r1c * ldb2 + kb + c1c * 16);            \
    } while (0)

    LOAD_STAGE(0, 0);  CP_COMMIT();
    LOAD_STAGE(1, 32); CP_COMMIT();

    for (int i = 0; i < niter; i++) {
        if (i < niter - 1) { CP_WAIT(1); } else { CP_WAIT(0); }
        __syncthreads();
        if (i + 2 < niter) { LOAD_STAGE((i + 2) % 3, (i + 2) * 32); CP_COMMIT(); }

        const uint32_t sA = sb + (i % 3) * STAGE_B;
        const uint32_t sB = sA + 16384;
#pragma unroll
        for (int h = 0; h < 2; h++) {
            uint32_t ah[4][4], al[4][4], bh[2][4];
            const int chk = 2 * h + (lane >> 4);
#pragma unroll
            for (int mt = 0; mt < 4; mt++) {
                const int r = wm * 64 + mt * 16 + (lane & 15);
                const uint32_t off = sw_off(r, chk);
                ldsm4(ah[mt], sA + off);
                ldsm4(al[mt], sA + 8192 + off);
            }
#pragma unroll
            for (int np = 0; np < 2; np++) {
                const int r = wn * 32 + np * 16 + (lane & 15);
                ldsm4(bh[np], sB + sw_off(r, chk));
            }
#pragma unroll
            for (int mt = 0; mt < 4; mt++)
#pragma unroll
                for (int nt = 0; nt < 4; nt++) {
                    const int np = nt >> 1, sel = nt & 1;
                    uint32_t bf[2] = { bh[np][sel], bh[np][sel + 2] };
                    mma16816h(acc[mt][nt], ah[mt], bf);
                    mma16816h(acc[mt][nt], al[mt], bf);
                }
        }
    }
#undef LOAD_STAGE

#pragma unroll
    for (int mt = 0; mt < 4; mt++) {
#pragma unroll
        for (int nt = 0; nt < 4; nt++) {
            const float* a = acc[mt][nt];
            const int gr = row0 + wm * 64 + mt * 16 + (lane >> 2);
            const int gc = col0 + wn * 32 + nt * 8 + (lane & 3) * 2;
            if (EPI == 2) {
                const float b0 = bias[gc], b1 = bias[gc + 1];
                size_t o = (size_t)gr * ldc + gc;
                *(__half2*)&Ch[o] = __halves2half2(__float2half(a[0] + b0),
                                                   __float2half(a[1] + b1));
                o = (size_t)(gr + 8) * ldc + gc;
                *(__half2*)&Ch[o] = __halves2half2(__float2half(a[2] + b0),
                                                   __float2half(a[3] + b1));
            } else {  // EPI == 3: V^T single store: out[b][dim][token]
#pragma unroll
                for (int q = 0; q < 4; q++) {
                    const int rr = gr + (q >> 1) * 8;
                    const int cc = gc + (q & 1);
                    const float t = a[q] + bias[cc];
                    const size_t o = (size_t)(rr >> 11) * ((size_t)HEAD_DIM * SEQ)
                                   + (size_t)cc * SEQ + (rr & (SEQ - 1));
                    Ch[o] = __float2half(t);
                }
            }
        }
    }
}

// K and V projections z-fused (z=0: K single store, z=1: V^T single store)
__global__ void __launch_bounds__(256, 2)
kv_proj(const __half* __restrict__ xkh, const __half* __restrict__ xkl,
        const __half* __restrict__ xvh, const __half* __restrict__ xvl,
        const __half* __restrict__ wk, const __half* __restrict__ wv,
        const float* __restrict__ bk, const float* __restrict__ bv,
        __half* __restrict__ k, __half* __restrict__ vt)
{
    if (blockIdx.z == 0)
        gemm_body<2>(xkh, xkl, wk, bk, k, D_MODEL, D_MODEL, D_MODEL, HEAD_DIM);
    else
        gemm_body<3>(xvh, xvl, wv, bv, vt, D_MODEL, D_MODEL, D_MODEL, 0);
}

// =====================================================================
// Fused flash attention (pure single-fp16 tensor ops, online softmax).
// CTA: 128 q rows x full KV sweep. 8 warps x 16 rows. KT=64 per iter.
// smem: 2 stages x 32KB (K 16K | Vt 16K) + Q 32KB @65536 = 96KB.
// Output: single fp16 (feeds single-A O-projection).
// =====================================================================
#define FL_STAGE  32768
#define FL_Q      65536
#define FL_SMEM   98304

__global__ void __launch_bounds__(256)
flash_mma(const __half* __restrict__ Qg,
          const __half* __restrict__ Kg, const __half* __restrict__ Vtg,
          __half* __restrict__ O)
{
    extern __shared__ char smem[];
    const uint32_t sb = smem_to_u32(smem);
    const int tid = threadIdx.x, lane = tid & 31, w = tid >> 5;
    const int q0 = blockIdx.x * 128;
    const int hh = blockIdx.y;
    const int b  = blockIdx.z;

    const char* pQ = (const char*)(Qg + ((size_t)(b * SEQ) + q0) * D_MODEL + hh * HEAD_DIM);
    const char* pK = (const char*)(Kg + (size_t)b * SEQ * HEAD_DIM);
    const char* pV = (const char*)(Vtg + (size_t)b * HEAD_DIM * SEQ);

#define LOAD_KV(stg, kv0) do {                                               \
        const uint32_t bb = sb + (uint32_t)(stg) * FL_STAGE;                 \
        _Pragma("unroll")                                                    \
        for (int i2 = 0; i2 < 4; i2++) {                                     \
            const int idx = tid + i2 * 256;                                  \
            const int r = idx >> 4, c = idx & 15;                            \
            const uint32_t d = bb + ((c >> 2) << 12) + sw_off(r, c & 3);     \
            const size_t so = (size_t)((kv0) + r) * 256 + (c & 3) * 16 + (c >> 2) * 64; \
            CP16(d, pK + so);                                                \
        }                                                                    \
        _Pragma("unroll")                                                    \
        for (int i2 = 0; i2 < 4; i2++) {                                     \
            const int idx = tid + i2 * 256;                                  \
            const int r = idx >> 3, c = idx & 7;                             \
            const uint32_t d = bb + 16384 + ((c >> 2) << 13) + sw_off(r, c & 3); \
            const size_t so = (size_t)r * (SEQ * 2) + (size_t)(kv0) * 2 + (c & 3) * 16 + (c >> 2) * 64; \
            CP16(d, pV + so);                                                \
        }                                                                    \
    } while (0)

    // stage Q once (single fp16, 32KB)
#pragma unroll
    for (int i2 = 0; i2 < 8; i2++) {
        const int idx = tid + i2 * 256;
        const int r = idx >> 4, c = idx & 15;
        const uint32_t d = sb + FL_Q + ((c >> 2) << 13) + sw_off(r, c & 3);
        const size_t so = (size_t)r * (D_MODEL * 2) + (c & 3) * 16 + (c >> 2) * 64;
        CP16(d, pQ + so);
    }
    CP_COMMIT();
    LOAD_KV(0, 0);
    CP_COMMIT();

    CP_WAIT(1);
    __syncthreads();

    // Q fragments: 8 k-steps
    uint32_t qf[8][4];
#pragma unroll
    for (int ks = 0; ks < 8; ks++) {
        const int blk = ks >> 1;
        const int c   = (ks & 1) * 2 + (lane >> 4);
        const int r   = w * 16 + (lane & 15);
        ldsm4(qf[ks], sb + FL_Q + (blk << 13) + sw_off(r, c));
    }

    float oacc[16][4];
#pragma unroll
    for (int nt = 0; nt < 16; nt++)
#pragma unroll
        for (int q = 0; q < 4; q++) oacc[nt][q] = 0.0f;
    float m0 = -1e30f, m1 = -1e30f, l0 = 0.0f, l1 = 0.0f;

    for (int it = 0; it < SEQ / 64; it++) {
        CP_WAIT(0);
        __syncthreads();
        if (it + 1 < SEQ / 64) { LOAD_KV((it + 1) & 1, (it + 1) * 64); CP_COMMIT(); }

        const uint32_t kb = sb + (uint32_t)(it & 1) * FL_STAGE;
        const uint32_t vb = kb + 16384;

        // -------- scores: S[16q x 64kv] = Q K^T --------
        float sacc[8][4];
#pragma unroll
        for (int nt = 0; nt < 8; nt++)
#pragma unroll
            for (int q = 0; q < 4; q++) sacc[nt][q] = 0.0f;

#pragma unroll
        for (int ks = 0; ks < 8; ks++) {
            const int blk = ks >> 1;
            const int cc  = (ks & 1) * 2 + (lane >> 4);
#pragma unroll
            for (int g = 0; g < 4; g++) {
                uint32_t kh4[4];
                const int r = g * 16 + (lane & 15);
                ldsm4(kh4, kb + (blk << 12) + sw_off(r, cc));
#pragma unroll
                for (int sel = 0; sel < 2; sel++) {
                    uint32_t f[2] = { kh4[sel], kh4[sel + 2] };
                    mma16816h(sacc[g * 2 + sel], qf[ks], f);
                }
            }
        }

        // -------- online softmax --------
        float mx0 = sacc[0][0], mx1 = sacc[0][2];
#pragma unroll
        for (int nt = 0; nt < 8; nt++) {
            mx0 = fmaxf(mx0, fmaxf(sacc[nt][0], sacc[nt][1]));
            mx1 = fmaxf(mx1, fmaxf(sacc[nt][2], sacc[nt][3]));
        }
        mx0 = fmaxf(mx0, __shfl_xor_sync(0xffffffffu, mx0, 1));
        mx0 = fmaxf(mx0, __shfl_xor_sync(0xffffffffu, mx0, 2));
        mx1 = fmaxf(mx1, __shfl_xor_sync(0xffffffffu, mx1, 1));
        mx1 = fmaxf(mx1, __shfl_xor_sync(0xffffffffu, mx1, 2));
        const float mn0 = fmaxf(m0, mx0), mn1 = fmaxf(m1, mx1);
        const float cr0 = __expf(m0 - mn0), cr1 = __expf(m1 - mn1);
        m0 = mn0; m1 = mn1;

        float s0 = 0.0f, s1 = 0.0f;
        uint32_t pp[8][2];
#pragma unroll
        for (int nt = 0; nt < 8; nt++) {
            const float p0 = __expf(sacc[nt][0] - mn0);
            const float p1 = __expf(sacc[nt][1] - mn0);
            const float p2 = __expf(sacc[nt][2] - mn1);
            const float p3 = __expf(sacc[nt][3] - mn1);
            s0 += p0 + p1;
            s1 += p2 + p3;
            __half2 x0 = __floats2half2_rn(p0, p1);
            __half2 x1 = __floats2half2_rn(p2, p3);
            pp[nt][0] = *(uint32_t*)&x0;
            pp[nt][1] = *(uint32_t*)&x1;
        }
        s0 += __shfl_xor_sync(0xffffffffu, s0, 1);
        s0 += __shfl_xor_sync(0xffffffffu, s0, 2);
        s1 += __shfl_xor_sync(0xffffffffu, s1, 1);
        s1 += __shfl_xor_sync(0xffffffffu, s1, 2);
        l0 = l0 * cr0 + s0;
        l1 = l1 * cr1 + s1;

#pragma unroll
        for (int nt = 0; nt < 16; nt++) {
            oacc[nt][0] *= cr0; oacc[nt][1] *= cr0;
            oacc[nt][2] *= cr1; oacc[nt][3] *= cr1;
        }

        // -------- PV: out += P[16x64] V[64x128] --------
#pragma unroll
        for (int kk = 0; kk < 4; kk++) {
            uint32_t ap[4] = { pp[2 * kk][0], pp[2 * kk][1],
                               pp[2 * kk + 1][0], pp[2 * kk + 1][1] };
            const int blk = kk >> 1;
            const int cc  = (kk & 1) * 2 + (lane >> 4);
#pragma unroll
            for (int g = 0; g < 8; g++) {
                uint32_t vh4[4];
                const int r = g * 16 + (lane & 15);
                ldsm4(vh4, vb + (blk << 13) + sw_off(r, cc));
#pragma unroll
                for (int sel = 0; sel < 2; sel++) {
                    uint32_t f[2] = { vh4[sel], vh4[sel + 2] };
                    mma16816h(oacc[g * 2 + sel], ap, f);
                }
            }
        }
    }
#undef LOAD_KV

    // -------- epilogue: normalize + single-fp16 store --------
    const float i0 = 1.0f / l0, i1 = 1.0f / l1;
    const size_t ro0 = ((size_t)(b * SEQ) + q0 + w * 16 + (lane >> 2)) * D_MODEL
                     + (size_t)hh * HEAD_DIM;
    const size_t ro1 = ro0 + (size_t)8 * D_MODEL;
#pragma unroll
    for (int nt = 0; nt < 16; nt++) {
        const int col = nt * 8 + (lane & 3) * 2;
        *(__half2*)&O[ro0 + col] = __floats2half2_rn(oacc[nt][0] * i0, oacc[nt][1] * i0);
        *(__half2*)&O[ro1 + col] = __floats2half2_rn(oacc[nt][2] * i1, oacc[nt][3] * i1);
    }
}

// =====================================================================
// launch
// =====================================================================
extern "C" void kernel_launch(void* const* d_in, const int* in_sizes, int n_in,
                              void* d_out, int out_size)
{
    const float* query = (const float*)d_in[0];
    const float* key   = (const float*)d_in[1];
    const float* value = (const float*)d_in[2];
    const float* Wq    = (const float*)d_in[3];
    const float* bq    = (const float*)d_in[4];
    const float* Wk    = (const float*)d_in[5];
    const float* bk    = (const float*)d_in[6];
    const float* Wv    = (const float*)d_in[7];
    const float* bv    = (const float*)d_in[8];
    const float* Wo    = (const float*)d_in[9];
    const float* bo    = (const float*)d_in[10];
    float* out = (float*)d_out;

    __half *xq, *xkh, *xkl, *xvh, *xvl;
    __half *wq, *wk, *wv, *wo;
    __half *q, *k, *vt, *a;
    cudaGetSymbolAddress((void**)&xq,  g_xq);
    cudaGetSymbolAddress((void**)&xkh, g_xk_h);  cudaGetSymbolAddress((void**)&xkl, g_xk_l);
    cudaGetSymbolAddress((void**)&xvh, g_xv_h);  cudaGetSymbolAddress((void**)&xvl, g_xv_l);
    cudaGetSymbolAddress((void**)&wq, g_wq);     cudaGetSymbolAddress((void**)&wk, g_wk);
    cudaGetSymbolAddress((void**)&wv, g_wv);     cudaGetSymbolAddress((void**)&wo, g_wo);
    cudaGetSymbolAddress((void**)&q,  g_q);
    cudaGetSymbolAddress((void**)&k,  g_k);      cudaGetSymbolAddress((void**)&vt, g_vt);
    cudaGetSymbolAddress((void**)&a,  g_a);

    cudaFuncSetAttribute(gemm_single<0>, cudaFuncAttributeMaxDynamicSharedMemorySize, SSM_BYTES);
    cudaFuncSetAttribute(gemm_single<2>, cudaFuncAttributeMaxDynamicSharedMemorySize, SSM_BYTES);
    cudaFuncSetAttribute(kv_proj,        cudaFuncAttributeMaxDynamicSharedMemorySize, GSM_BYTES);
    cudaFuncSetAttribute(flash_mma,      cudaFuncAttributeMaxDynamicSharedMemorySize, FL_SMEM);

    const float attn_scale = 0.08838834764831845f;  // 1/sqrt(128)

    // 1) input conversions (z=0: query single; z=1,2: key/value split)
    conv_all<<<dim3(NELEM_X / 1024, 3), 256>>>(query, key, value,
                                               xq, xkh, xkl, xvh, xvl);

    // 2) weight transposes -> single fp16
    convT_big<<<dim3(D_MODEL / 32, D_MODEL / 32, 2), 256>>>(Wq, Wo, wq, wo);
    convT_small<<<dim3(HEAD_DIM / 32, D_MODEL / 32, 2), 256>>>(Wk, Wv, wk, wv);

    // 3) Q projection (single-A, scaled by 1/sqrt(d), single fp16 out)
    gemm_single<2><<<dim3(D_MODEL / 128, MROWS / 128), 256, SSM_BYTES>>>(
        xq, wq, bq, nullptr, q,
        D_MODEL, D_MODEL, D_MODEL, D_MODEL, attn_scale);

    // 4) K + V projections (split-A kept; V stored transposed)
    kv_proj<<<dim3(1, MROWS / 128, 2), 256, GSM_BYTES>>>(
        xkh, xkl, xvh, xvl, wk, wv, bk, bv, k, vt);

    // 5) fused flash attention (single-fp16) -> single fp16 attn output
    flash_mma<<<dim3(SEQ / 128, NUM_HEADS, BATCH), 256, FL_SMEM>>>(
        q, k, vt, a);

    // 6) output projection (single-A) -> d_out (fp32 + bias)
    gemm_single<0><<<dim3(D_MODEL / 128, MROWS / 128), 256, SSM_BYTES>>>(
        a, wo, bo, out, nullptr,
        D_MODEL, D_MODEL, D_MODEL, D_MODEL, 1.0f);
}

// round 14
// speedup vs baseline: 2.4845x; 1.0727x over previous
#include <cuda_runtime.h>
#include <cuda_fp16.h>
#include <math.h>
#include <stdint.h>

// ---------------- problem constants ----------------
#define D_MODEL   2048
#define NUM_HEADS 16
#define HEAD_DIM  128
#define BATCH     2
#define SEQ       2048
#define MROWS     (BATCH * SEQ)        // 4096

#define NELEM_X   (MROWS * D_MODEL)          // 8388608
#define NELEM_W   (D_MODEL * D_MODEL)        // 4194304
#define NELEM_WKV (D_MODEL * HEAD_DIM)       // 262144
#define NELEM_KV  (MROWS * HEAD_DIM)         // 524288

// ---------------- scratch (__device__ statics; no cudaMalloc) ----------
__device__ __align__(16) __half g_xq[NELEM_X];                      // query single
__device__ __align__(16) __half g_xk_h[NELEM_X], g_xk_l[NELEM_X];   // key split
__device__ __align__(16) __half g_xv_h[NELEM_X], g_xv_l[NELEM_X];   // value split
__device__ __align__(16) __half g_wq[NELEM_W];        // [N,K] single fp16
__device__ __align__(16) __half g_wk[NELEM_WKV];
__device__ __align__(16) __half g_wv[NELEM_WKV];
__device__ __align__(16) __half g_wo[NELEM_W];
__device__ __align__(16) __half g_q[NELEM_X];                       // pre-scaled Q single
__device__ __align__(16) __half g_k[NELEM_KV];                      // K single [b*s, d]
__device__ __align__(16) __half g_vt[NELEM_KV];                     // V^T single [b][d, s]
__device__ __align__(16) __half g_a[NELEM_X];                       // attn out single

// ---------------- low-level helpers ----------
__device__ __forceinline__ uint32_t smem_to_u32(const void* p) {
    uint32_t a;
    asm("{ .reg .u64 t; cvta.to.shared.u64 t, %1; cvt.u32.u64 %0, t; }" : "=r"(a) : "l"(p));
    return a;
}
#define CP16(dst, src) \
    asm volatile("cp.async.cg.shared.global [%0], [%1], 16;" :: "r"(dst), "l"(src))
#define CP_COMMIT() asm volatile("cp.async.commit_group;" ::: "memory")
#define CP_WAIT(n)  asm volatile("cp.async.wait_group %0;" :: "n"(n) : "memory")

__device__ __forceinline__ void ldsm4(uint32_t* r, uint32_t addr) {
    asm volatile("ldmatrix.sync.aligned.m8n8.x4.shared.b16 {%0,%1,%2,%3}, [%4];"
        : "=r"(r[0]), "=r"(r[1]), "=r"(r[2]), "=r"(r[3]) : "r"(addr));
}
// fp16 inputs, fp32 accumulate
__device__ __forceinline__ void mma16816h(float* c, const uint32_t* a, const uint32_t* b) {
    asm volatile("mma.sync.aligned.m16n8k16.row.col.f32.f16.f16.f32 "
        "{%0,%1,%2,%3}, {%4,%5,%6,%7}, {%8,%9}, {%0,%1,%2,%3};"
        : "+f"(c[0]), "+f"(c[1]), "+f"(c[2]), "+f"(c[3])
        : "r"(a[0]), "r"(a[1]), "r"(a[2]), "r"(a[3]), "r"(b[0]), "r"(b[1]));
}

__device__ __forceinline__ void split2h(float t0, float t1, __half2& hi, __half2& lo) {
    __half h0 = __float2half(t0);
    __half h1 = __float2half(t1);
    hi = __halves2half2(h0, h1);
    lo = __halves2half2(__float2half(t0 - __half2float(h0)),
                        __float2half(t1 - __half2float(h1)));
}

// swizzled smem offset for (row r, 16B-chunk c) within a 64B-wide tile block
__device__ __forceinline__ uint32_t sw_off(int r, int c) {
    return (uint32_t)(r * 64 + ((c ^ ((r >> 1) & 3)) << 4));
}

// =====================================================================
// Combined conversion kernel (ONE launch):
//   [0, 8192)       : convT Wq / Wo  (z = bid>>12, 64x64 blocks each)
//   [8192, 8704)    : convT Wk / Wv  (z = rel>>8,  4x64 blocks each)
//   [8704, 33280)   : input conv     (z = rel>>13: q single, k split, v split)
// =====================================================================
__device__ __forceinline__ void convT_body(
    const float* __restrict__ W, __half* __restrict__ Th, int Kd, int Nd,
    int bx, int by)
{
    __shared__ float t[32][33];
    const int n0 = bx * 32, k0 = by * 32;
    const int tx = threadIdx.x & 31, ty = threadIdx.x >> 5;
#pragma unroll
    for (int i = 0; i < 4; i++)
        t[ty + i * 8][tx] = W[(size_t)(k0 + ty + i * 8) * Nd + n0 + tx];
    __syncthreads();
#pragma unroll
    for (int i = 0; i < 4; i++) {
        float v = t[tx][ty + i * 8];
        Th[(size_t)(n0 + ty + i * 8) * Kd + k0 + tx] = __float2half(v);
    }
}

__global__ void __launch_bounds__(256)
conv_combined(const float* __restrict__ query, const float* __restrict__ key,
              const float* __restrict__ value,
              const float* __restrict__ Wq, const float* __restrict__ Wk,
              const float* __restrict__ Wv, const float* __restrict__ Wo,
              __half* __restrict__ xq,
              __half* __restrict__ xkh, __half* __restrict__ xkl,
              __half* __restrict__ xvh, __half* __restrict__ xvl,
              __half* __restrict__ wq, __half* __restrict__ wk,
              __half* __restrict__ wv, __half* __restrict__ wo)
{
    const int bid = blockIdx.x;
    if (bid < 8192) {                 // big weight transposes
        const int z = bid >> 12;
        const int r = bid & 4095;
        convT_body(z ? Wo : Wq, z ? wo : wq, D_MODEL, D_MODEL, r & 63, r >> 6);
        return;
    }
    if (bid < 8704) {                 // small weight transposes
        const int r = bid - 8192;
        const int z = r >> 8;
        const int rr = r & 255;
        convT_body(z ? Wv : Wk, z ? wv : wk, D_MODEL, HEAD_DIM, rr & 3, rr >> 2);
        return;
    }
    // input conversions
    const int r = bid - 8704;
    const int z = r >> 13;            // 0: query, 1: key, 2: value
    const int i = (r & 8191) * 256 + threadIdx.x;
    if (z == 0) {
        float4 val = ((const float4*)query)[i];
        ((__half2*)xq)[i * 2]     = __floats2half2_rn(val.x, val.y);
        ((__half2*)xq)[i * 2 + 1] = __floats2half2_rn(val.z, val.w);
        return;
    }
    const float* x = (z == 1) ? key : value;
    __half* h = (z == 1) ? xkh : xvh;
    __half* l = (z == 1) ? xkl : xvl;
    float4 val = ((const float4*)x)[i];
    __half2 h0, h1, l0, l1;
    split2h(val.x, val.y, h0, l0);
    split2h(val.z, val.w, h1, l1);
    ((__half2*)h)[i * 2]     = h0;
    ((__half2*)h)[i * 2 + 1] = h1;
    ((__half2*)l)[i * 2]     = l0;
    ((__half2*)l)[i * 2 + 1] = l1;
}

// =====================================================================
// SINGLE-fp16 GEMM body: C = A[M,K] @ B[N,K]^T (+bias)(*scale)
// CTA 128x128, BK=32, 3-stage cp.async, 8 warps (64x32 warp tile).
// EPI: 0 = fp32+bias, 2 = fp16 single (+bias, *scale).
// =====================================================================
#define SSTAGE_B   16384                      // A 8K | B 8K
#define SSM_BYTES  (3 * SSTAGE_B)             // 49152

template<int EPI>
__device__ __forceinline__ void gemm_single_body(
            const __half* __restrict__ A, const __half* __restrict__ B,
            const float* __restrict__ bias,
            float* __restrict__ Cf, __half* __restrict__ Ch,
            int K, int lda, int ldb, int ldc, float scale,
            int row0, int col0)
{
    extern __shared__ char smem[];
    const uint32_t sb = smem_to_u32(smem);
    const int tid = threadIdx.x, lane = tid & 31, wid = tid >> 5;
    const int wm = wid & 1, wn = wid >> 1;

    const char* pA = (const char*)(A + (size_t)row0 * lda);
    const char* pB = (const char*)(B + (size_t)col0 * ldb);
    const size_t lda2 = (size_t)lda * 2, ldb2 = (size_t)ldb * 2;

    const int r0c = tid >> 2,            c0c = tid & 3;
    const int r1c = (tid + 256) >> 2,    c1c = (tid + 256) & 3;
    const uint32_t so0 = sw_off(r0c, c0c), so1 = sw_off(r1c, c1c);

    float acc[4][4][4];
#pragma unroll
    for (int a = 0; a < 4; a++)
#pragma unroll
        for (int b = 0; b < 4; b++)
#pragma unroll
            for (int c = 0; c < 4; c++) acc[a][b][c] = 0.0f;

    const int niter = K >> 5;

#define LOAD_S(s, kof) do {                                                  \
        const uint32_t bA = sb + (s) * SSTAGE_B;                             \
        const size_t kb = (size_t)(kof) * 2;                                 \
        CP16(bA + so0,        pA + r0c * lda2 + kb + c0c * 16);              \
        CP16(bA + so1,        pA + r1c * lda2 + kb + c1c * 16);              \
        CP16(bA + 8192 + so0, pB + r0c * ldb2 + kb + c0c * 16);              \
        CP16(bA + 8192 + so1, pB + r1c * ldb2 + kb + c1c * 16);              \
    } while (0)

    LOAD_S(0, 0);  CP_COMMIT();
    LOAD_S(1, 32); CP_COMMIT();

    for (int i = 0; i < niter; i++) {
        if (i < niter - 1) { CP_WAIT(1); } else { CP_WAIT(0); }
        __syncthreads();
        if (i + 2 < niter) { LOAD_S((i + 2) % 3, (i + 2) * 32); CP_COMMIT(); }

        const uint32_t sA = sb + (i % 3) * SSTAGE_B;
        const uint32_t sB = sA + 8192;
#pragma unroll
        for (int h = 0; h < 2; h++) {
            uint32_t ah[4][4], bh[2][4];
            const int chk = 2 * h + (lane >> 4);
#pragma unroll
            for (int mt = 0; mt < 4; mt++) {
                const int r = wm * 64 + mt * 16 + (lane & 15);
                ldsm4(ah[mt], sA + sw_off(r, chk));
            }
#pragma unroll
            for (int np = 0; np < 2; np++) {
                const int r = wn * 32 + np * 16 + (lane & 15);
                ldsm4(bh[np], sB + sw_off(r, chk));
            }
#pragma unroll
            for (int mt = 0; mt < 4; mt++)
#pragma unroll
                for (int nt = 0; nt < 4; nt++) {
                    const int np = nt >> 1, sel = nt & 1;
                    uint32_t bf[2] = { bh[np][sel], bh[np][sel + 2] };
                    mma16816h(acc[mt][nt], ah[mt], bf);
                }
        }
    }
#undef LOAD_S

#pragma unroll
    for (int mt = 0; mt < 4; mt++) {
#pragma unroll
        for (int nt = 0; nt < 4; nt++) {
            const float* a = acc[mt][nt];
            const int gr = row0 + wm * 64 + mt * 16 + (lane >> 2);
            const int gc = col0 + wn * 32 + nt * 8 + (lane & 3) * 2;
            if (EPI == 0) {
                float b0 = bias[gc], b1 = bias[gc + 1];
                float2 v0 = { a[0] + b0, a[1] + b1 };
                float2 v1 = { a[2] + b0, a[3] + b1 };
                *(float2*)&Cf[(size_t)gr * ldc + gc]       = v0;
                *(float2*)&Cf[(size_t)(gr + 8) * ldc + gc] = v1;
            } else {
                const float b0 = bias[gc], b1 = bias[gc + 1];
                size_t o = (size_t)gr * ldc + gc;
                *(__half2*)&Ch[o] = __halves2half2(__float2half((a[0] + b0) * scale),
                                                   __float2half((a[1] + b1) * scale));
                o = (size_t)(gr + 8) * ldc + gc;
                *(__half2*)&Ch[o] = __halves2half2(__float2half((a[2] + b0) * scale),
                                                   __float2half((a[3] + b1) * scale));
            }
        }
    }
}

// =====================================================================
// 2-term split-fp16 GEMM body for K/V projections (A split, B single).
// EPI: 2 = fp16 single (+bias), 3 = fp16 single transposed V^T (+bias).
// =====================================================================
#define STAGE_B    24576                      // Ah 8K | Al 8K | Bh 8K
#define GSM_BYTES  (3 * STAGE_B)              // 73728

template<int EPI>
__device__ __forceinline__ void gemm_body(
         const __half* __restrict__ Ah, const __half* __restrict__ Al,
         const __half* __restrict__ Bh,
         const float* __restrict__ bias,
         __half* __restrict__ Ch,
         int K, int lda, int ldb, int ldc, int row0, int col0)
{
    extern __shared__ char smem[];
    const uint32_t sb = smem_to_u32(smem);
    const int tid = threadIdx.x, lane = tid & 31, wid = tid >> 5;
    const int wm = wid & 1, wn = wid >> 1;

    const char* pAh = (const char*)(Ah + (size_t)row0 * lda);
    const char* pAl = (const char*)(Al + (size_t)row0 * lda);
    const char* pBh = (const char*)(Bh + (size_t)col0 * ldb);
    const size_t lda2 = (size_t)lda * 2, ldb2 = (size_t)ldb * 2;

    const int r0c = tid >> 2,            c0c = tid & 3;
    const int r1c = (tid + 256) >> 2,    c1c = (tid + 256) & 3;
    const uint32_t so0 = sw_off(r0c, c0c), so1 = sw_off(r1c, c1c);

    float acc[4][4][4];
#pragma unroll
    for (int a = 0; a < 4; a++)
#pragma unroll
        for (int b = 0; b < 4; b++)
#pragma unroll
            for (int c = 0; c < 4; c++) acc[a][b][c] = 0.0f;

    const int niter = K >> 5;

#define LOAD_STAGE(s, kof) do {                                              \
        const uint32_t bA = sb + (s) * STAGE_B;                              \
        const size_t kb = (size_t)(kof) * 2;                                 \
        CP16(bA + so0,         pAh + r0c * lda2 + kb + c0c * 16);            \
        CP16(bA + so1,         pAh + r1c * lda2 + kb + c1c * 16);            \
        CP16(bA + 8192 + so0,  pAl + r0c * lda2 + kb + c0c * 16);            \
        CP16(bA + 8192 + so1,  pAl + r1c * lda2 + kb + c1c * 16);            \
        CP16(bA + 16384 + so0, pBh + r0c * ldb2 + kb + c0c * 16);            \
        CP16(bA + 16384 + so1, pBh + r1c * ldb2 + kb + c1c * 16);            \
    } while (0)

    LOAD_STAGE(0, 0);  CP_COMMIT();
    LOAD_STAGE(1, 32); CP_COMMIT();

    for (int i = 0; i < niter; i++) {
        if (i < niter - 1) { CP_WAIT(1); } else { CP_WAIT(0); }
        __syncthreads();
        if (i + 2 < niter) { LOAD_STAGE((i + 2) % 3, (i + 2) * 32); CP_COMMIT(); }

        const uint32_t sA = sb + (i % 3) * STAGE_B;
        const uint32_t sB = sA + 16384;
#pragma unroll
        for (int h = 0; h < 2; h++) {
            uint32_t ah[4][4], al[4][4], bh[2][4];
            const int chk = 2 * h + (lane >> 4);
#pragma unroll
            for (int mt = 0; mt < 4; mt++) {
                const int r = wm * 64 + mt * 16 + (lane & 15);
                const uint32_t off = sw_off(r, chk);
                ldsm4(ah[mt], sA + off);
                ldsm4(al[mt], sA + 8192 + off);
            }
#pragma unroll
            for (int np = 0; np < 2; np++) {
                const int r = wn * 32 + np * 16 + (lane & 15);
                ldsm4(bh[np], sB + sw_off(r, chk));
            }
#pragma unroll
            for (int mt = 0; mt < 4; mt++)
#pragma unroll
                for (int nt = 0; nt < 4; nt++) {
                    const int np = nt >> 1, sel = nt & 1;
                    uint32_t bf[2] = { bh[np][sel], bh[np][sel + 2] };
                    mma16816h(acc[mt][nt], ah[mt], bf);
                    mma16816h(acc[mt][nt], al[mt], bf);
                }
        }
    }
#undef LOAD_STAGE

#pragma unroll
    for (int mt = 0; mt < 4; mt++) {
#pragma unroll
        for (int nt = 0; nt < 4; nt++) {
            const float* a = acc[mt][nt];
            const int gr = row0 + wm * 64 + mt * 16 + (lane >> 2);
            const int gc = col0 + wn * 32 + nt * 8 + (lane & 3) * 2;
            if (EPI == 2) {
                const float b0 = bias[gc], b1 = bias[gc + 1];
                size_t o = (size_t)gr * ldc + gc;
                *(__half2*)&Ch[o] = __halves2half2(__float2half(a[0] + b0),
                                                   __float2half(a[1] + b1));
                o = (size_t)(gr + 8) * ldc + gc;
                *(__half2*)&Ch[o] = __halves2half2(__float2half(a[2] + b0),
                                                   __float2half(a[3] + b1));
            } else {  // EPI == 3: V^T single store: out[b][dim][token]
#pragma unroll
                for (int q = 0; q < 4; q++) {
                    const int rr = gr + (q >> 1) * 8;
                    const int cc = gc + (q & 1);
                    const float t = a[q] + bias[cc];
                    const size_t o = (size_t)(rr >> 11) * ((size_t)HEAD_DIM * SEQ)
                                   + (size_t)cc * SEQ + (rr & (SEQ - 1));
                    Ch[o] = __float2half(t);
                }
            }
        }
    }
}

// =====================================================================
// Combined projections (ONE launch, 576 blocks):
//   [0, 32)    : K projection  (split-A, long blocks — start first)
//   [32, 64)   : V projection  (split-A, transposed store)
//   [64, 576)  : Q projection  (single-A, scaled)
// =====================================================================
__global__ void __launch_bounds__(256, 2)
proj_combined(const __half* __restrict__ xq,
              const __half* __restrict__ xkh, const __half* __restrict__ xkl,
              const __half* __restrict__ xvh, const __half* __restrict__ xvl,
              const __half* __restrict__ wq, const __half* __restrict__ wk,
              const __half* __restrict__ wv,
              const float* __restrict__ bq, const float* __restrict__ bk,
              const float* __restrict__ bv,
              __half* __restrict__ q, __half* __restrict__ k,
              __half* __restrict__ vt, float scale)
{
    const int bid = blockIdx.x;
    if (bid < 32) {
        gemm_body<2>(xkh, xkl, wk, bk, k,
                     D_MODEL, D_MODEL, D_MODEL, HEAD_DIM, bid * 128, 0);
    } else if (bid < 64) {
        gemm_body<3>(xvh, xvl, wv, bv, vt,
                     D_MODEL, D_MODEL, D_MODEL, 0, (bid - 32) * 128, 0);
    } else {
        const int r = bid - 64;
        gemm_single_body<2>(xq, wq, bq, nullptr, q,
                            D_MODEL, D_MODEL, D_MODEL, D_MODEL, scale,
                            (r >> 4) * 128, (r & 15) * 128);
    }
}

// O-projection (separate: depends on flash output)
__global__ void __launch_bounds__(256, 2)
o_proj(const __half* __restrict__ A, const __half* __restrict__ B,
       const float* __restrict__ bias, float* __restrict__ Cf)
{
    gemm_single_body<0>(A, B, bias, Cf, nullptr,
                        D_MODEL, D_MODEL, D_MODEL, D_MODEL, 1.0f,
                        blockIdx.y * 128, blockIdx.x * 128);
}

// =====================================================================
// Fused flash attention (pure single-fp16 tensor ops, online softmax).
// CTA: 128 q rows x full KV sweep. 8 warps x 16 rows. KT=64 per iter.
// smem: 2 stages x 32KB (K 16K | Vt 16K) + Q 32KB @65536 = 96KB.
// =====================================================================
#define FL_STAGE  32768
#define FL_Q      65536
#define FL_SMEM   98304

__global__ void __launch_bounds__(256)
flash_mma(const __half* __restrict__ Qg,
          const __half* __restrict__ Kg, const __half* __restrict__ Vtg,
          __half* __restrict__ O)
{
    extern __shared__ char smem[];
    const uint32_t sb = smem_to_u32(smem);
    const int tid = threadIdx.x, lane = tid & 31, w = tid >> 5;
    const int q0 = blockIdx.x * 128;
    const int hh = blockIdx.y;
    const int b  = blockIdx.z;

    const char* pQ = (const char*)(Qg + ((size_t)(b * SEQ) + q0) * D_MODEL + hh * HEAD_DIM);
    const char* pK = (const char*)(Kg + (size_t)b * SEQ * HEAD_DIM);
    const char* pV = (const char*)(Vtg + (size_t)b * HEAD_DIM * SEQ);

#define LOAD_KV(stg, kv0) do {                                               \
        const uint32_t bb = sb + (uint32_t)(stg) * FL_STAGE;                 \
        _Pragma("unroll")                                                    \
        for (int i2 = 0; i2 < 4; i2++) {                                     \
            const int idx = tid + i2 * 256;                                  \
            const int r = idx >> 4, c = idx & 15;                            \
            const uint32_t d = bb + ((c >> 2) << 12) + sw_off(r, c & 3);     \
            const size_t so = (size_t)((kv0) + r) * 256 + (c & 3) * 16 + (c >> 2) * 64; \
            CP16(d, pK + so);                                                \
        }                                                                    \
        _Pragma("unroll")                                                    \
        for (int i2 = 0; i2 < 4; i2++) {                                     \
            const int idx = tid + i2 * 256;                                  \
            const int r = idx >> 3, c = idx & 7;                             \
            const uint32_t d = bb + 16384 + ((c >> 2) << 13) + sw_off(r, c & 3); \
            const size_t so = (size_t)r * (SEQ * 2) + (size_t)(kv0) * 2 + (c & 3) * 16 + (c >> 2) * 64; \
            CP16(d, pV + so);                                                \
        }                                                                    \
    } while (0)

    // stage Q once (single fp16, 32KB)
#pragma unroll
    for (int i2 = 0; i2 < 8; i2++) {
        const int idx = tid + i2 * 256;
        const int r = idx >> 4, c = idx & 15;
        const uint32_t d = sb + FL_Q + ((c >> 2) << 13) + sw_off(r, c & 3);
        const size_t so = (size_t)r * (D_MODEL * 2) + (c & 3) * 16 + (c >> 2) * 64;
        CP16(d, pQ + so);
    }
    CP_COMMIT();
    LOAD_KV(0, 0);
    CP_COMMIT();

    CP_WAIT(1);
    __syncthreads();

    // Q fragments: 8 k-steps
    uint32_t qf[8][4];
#pragma unroll
    for (int ks = 0; ks < 8; ks++) {
        const int blk = ks >> 1;
        const int c   = (ks & 1) * 2 + (lane >> 4);
        const int r   = w * 16 + (lane & 15);
        ldsm4(qf[ks], sb + FL_Q + (blk << 13) + sw_off(r, c));
    }

    float oacc[16][4];
#pragma unroll
    for (int nt = 0; nt < 16; nt++)
#pragma unroll
        for (int q = 0; q < 4; q++) oacc[nt][q] = 0.0f;
    float m0 = -1e30f, m1 = -1e30f, l0 = 0.0f, l1 = 0.0f;

    for (int it = 0; it < SEQ / 64; it++) {
        CP_WAIT(0);
        __syncthreads();
        if (it + 1 < SEQ / 64) { LOAD_KV((it + 1) & 1, (it + 1) * 64); CP_COMMIT(); }

        const uint32_t kb = sb + (uint32_t)(it & 1) * FL_STAGE;
        const uint32_t vb = kb + 16384;

        // -------- scores: S[16q x 64kv] = Q K^T --------
        float sacc[8][4];
#pragma unroll
        for (int nt = 0; nt < 8; nt++)
#pragma unroll
            for (int q = 0; q < 4; q++) sacc[nt][q] = 0.0f;

#pragma unroll
        for (int ks = 0; ks < 8; ks++) {
            const int blk = ks >> 1;
            const int cc  = (ks & 1) * 2 + (lane >> 4);
#pragma unroll
            for (int g = 0; g < 4; g++) {
                uint32_t kh4[4];
                const int r = g * 16 + (lane & 15);
                ldsm4(kh4, kb + (blk << 12) + sw_off(r, cc));
#pragma unroll
                for (int sel = 0; sel < 2; sel++) {
                    uint32_t f[2] = { kh4[sel], kh4[sel + 2] };
                    mma16816h(sacc[g * 2 + sel], qf[ks], f);
                }
            }
        }

        // -------- online softmax --------
        float mx0 = sacc[0][0], mx1 = sacc[0][2];
#pragma unroll
        for (int nt = 0; nt < 8; nt++) {
            mx0 = fmaxf(mx0, fmaxf(sacc[nt][0], sacc[nt][1]));
            mx1 = fmaxf(mx1, fmaxf(sacc[nt][2], sacc[nt][3]));
        }
        mx0 = fmaxf(mx0, __shfl_xor_sync(0xffffffffu, mx0, 1));
        mx0 = fmaxf(mx0, __shfl_xor_sync(0xffffffffu, mx0, 2));
        mx1 = fmaxf(mx1, __shfl_xor_sync(0xffffffffu, mx1, 1));
        mx1 = fmaxf(mx1, __shfl_xor_sync(0xffffffffu, mx1, 2));
        const float mn0 = fmaxf(m0, mx0), mn1 = fmaxf(m1, mx1);
        const float cr0 = __expf(m0 - mn0), cr1 = __expf(m1 - mn1);
        m0 = mn0; m1 = mn1;

        float s0 = 0.0f, s1 = 0.0f;
        uint32_t pp[8][2];
#pragma unroll
        for (int nt = 0; nt < 8; nt++) {
            const float p0 = __expf(sacc[nt][0] - mn0);
            const float p1 = __expf(sacc[nt][1] - mn0);
            const float p2 = __expf(sacc[nt][2] - mn1);
            const float p3 = __expf(sacc[nt][3] - mn1);
            s0 += p0 + p1;
            s1 += p2 + p3;
            __half2 x0 = __floats2half2_rn(p0, p1);
            __half2 x1 = __floats2half2_rn(p2, p3);
            pp[nt][0] = *(uint32_t*)&x0;
            pp[nt][1] = *(uint32_t*)&x1;
        }
        s0 += __shfl_xor_sync(0xffffffffu, s0, 1);
        s0 += __shfl_xor_sync(0xffffffffu, s0, 2);
        s1 += __shfl_xor_sync(0xffffffffu, s1, 1);
        s1 += __shfl_xor_sync(0xffffffffu, s1, 2);
        l0 = l0 * cr0 + s0;
        l1 = l1 * cr1 + s1;

#pragma unroll
        for (int nt = 0; nt < 16; nt++) {
            oacc[nt][0] *= cr0; oacc[nt][1] *= cr0;
            oacc[nt][2] *= cr1; oacc[nt][3] *= cr1;
        }

        // -------- PV: out += P[16x64] V[64x128] --------
#pragma unroll
        for (int kk = 0; kk < 4; kk++) {
            uint32_t ap[4] = { pp[2 * kk][0], pp[2 * kk][1],
                               pp[2 * kk + 1][0], pp[2 * kk + 1][1] };
            const int blk = kk >> 1;
            const int cc  = (kk & 1) * 2 + (lane >> 4);
#pragma unroll
            for (int g = 0; g < 8; g++) {
                uint32_t vh4[4];
                const int r = g * 16 + (lane & 15);
                ldsm4(vh4, vb + (blk << 13) + sw_off(r, cc));
#pragma unroll
                for (int sel = 0; sel < 2; sel++) {
                    uint32_t f[2] = { vh4[sel], vh4[sel + 2] };
                    mma16816h(oacc[g * 2 + sel], ap, f);
                }
            }
        }
    }
#undef LOAD_KV

    // -------- epilogue: normalize + single-fp16 store --------
    const float i0 = 1.0f / l0, i1 = 1.0f / l1;
    const size_t ro0 = ((size_t)(b * SEQ) + q0 + w * 16 + (lane >> 2)) * D_MODEL
                     + (size_t)hh * HEAD_DIM;
    const size_t ro1 = ro0 + (size_t)8 * D_MODEL;
#pragma unroll
    for (int nt = 0; nt < 16; nt++) {
        const int col = nt * 8 + (lane & 3) * 2;
        *(__half2*)&O[ro0 + col] = __floats2half2_rn(oacc[nt][0] * i0, oacc[nt][1] * i0);
        *(__half2*)&O[ro1 + col] = __floats2half2_rn(oacc[nt][2] * i1, oacc[nt][3] * i1);
    }
}

// =====================================================================
// launch (4 kernels total)
// =====================================================================
extern "C" void kernel_launch(void* const* d_in, const int* in_sizes, int n_in,
                              void* d_out, int out_size)
{
    const float* query = (const float*)d_in[0];
    const float* key   = (const float*)d_in[1];
    const float* value = (const float*)d_in[2];
    const float* Wq    = (const float*)d_in[3];
    const float* bq    = (const float*)d_in[4];
    const float* Wk    = (const float*)d_in[5];
    const float* bk    = (const float*)d_in[6];
    const float* Wv    = (const float*)d_in[7];
    const float* bv    = (const float*)d_in[8];
    const float* Wo    = (const float*)d_in[9];
    const float* bo    = (const float*)d_in[10];
    float* out = (float*)d_out;

    __half *xq, *xkh, *xkl, *xvh, *xvl;
    __half *wq, *wk, *wv, *wo;
    __half *q, *k, *vt, *a;
    cudaGetSymbolAddress((void**)&xq,  g_xq);
    cudaGetSymbolAddress((void**)&xkh, g_xk_h);  cudaGetSymbolAddress((void**)&xkl, g_xk_l);
    cudaGetSymbolAddress((void**)&xvh, g_xv_h);  cudaGetSymbolAddress((void**)&xvl, g_xv_l);
    cudaGetSymbolAddress((void**)&wq, g_wq);     cudaGetSymbolAddress((void**)&wk, g_wk);
    cudaGetSymbolAddress((void**)&wv, g_wv);     cudaGetSymbolAddress((void**)&wo, g_wo);
    cudaGetSymbolAddress((void**)&q,  g_q);
    cudaGetSymbolAddress((void**)&k,  g_k);      cudaGetSymbolAddress((void**)&vt, g_vt);
    cudaGetSymbolAddress((void**)&a,  g_a);

    cudaFuncSetAttribute(proj_combined, cudaFuncAttributeMaxDynamicSharedMemorySize, GSM_BYTES);
    cudaFuncSetAttribute(o_proj,        cudaFuncAttributeMaxDynamicSharedMemorySize, SSM_BYTES);
    cudaFuncSetAttribute(flash_mma,     cudaFuncAttributeMaxDynamicSharedMemorySize, FL_SMEM);

    const float attn_scale = 0.08838834764831845f;  // 1/sqrt(128)

    // 1) all conversions, one launch
    conv_combined<<<33280, 256>>>(query, key, value, Wq, Wk, Wv, Wo,
                                  xq, xkh, xkl, xvh, xvl, wq, wk, wv, wo);

    // 2) Q + K + V projections, one launch (kv blocks first to overlap)
    proj_combined<<<576, 256, GSM_BYTES>>>(
        xq, xkh, xkl, xvh, xvl, wq, wk, wv, bq, bk, bv, q, k, vt, attn_scale);

    // 3) fused flash attention
    flash_mma<<<dim3(SEQ / 128, NUM_HEADS, BATCH), 256, FL_SMEM>>>(
        q, k, vt, a);

    // 4) output projection -> d_out (fp32 + bias)
    o_proj<<<dim3(D_MODEL / 128, MROWS / 128), 256, SSM_BYTES>>>(a, wo, bo, out);
}